// round 2
// baseline (speedup 1.0000x reference)
#include <cuda_runtime.h>
#include <math.h>

#define D_MODEL 4096
#define N_TOK   4096   // B*T
#define T_SEQ   2048
#define N_HEAD  32
#define H_DIM   128

// Scratch (allocation-free rule: __device__ globals)
__device__ float g_q[(size_t)N_TOK * D_MODEL];
__device__ float g_k[(size_t)N_TOK * H_DIM];
__device__ float g_v[(size_t)N_TOK * H_DIM];
__device__ float g_attn[(size_t)N_TOK * D_MODEL];

// ---------------------------------------------------------------------------
// SGEMM: C[M,N] = A[M,K] @ W[N,K]^T + bias[N]
// 128x128 block, BK=16, 256 threads, 8x8 per thread, fp32 FFMA.
// ---------------------------------------------------------------------------
__global__ __launch_bounds__(256) void sgemm_bias_kernel(
    const float* __restrict__ A, const float* __restrict__ W,
    const float* __restrict__ bias, float* __restrict__ C,
    int M, int N, int K)
{
    __shared__ float As[16 * 132];   // As[k][m], stride 132 (aligned float4, 2-way store conflicts)
    __shared__ float Ws[16 * 132];   // Ws[k][n]

    const int tid = threadIdx.x;
    const int tx = tid & 15;
    const int ty = tid >> 4;
    const int m0 = blockIdx.y << 7;
    const int n0 = blockIdx.x << 7;
    const int lr = tid >> 2;          // 0..63
    const int lk = (tid & 3) << 2;    // 0,4,8,12

    float acc[8][8];
#pragma unroll
    for (int i = 0; i < 8; i++)
#pragma unroll
        for (int j = 0; j < 8; j++) acc[i][j] = 0.0f;

    const float* Ap = A + (size_t)(m0 + lr) * K + lk;
    const float* Wp = W + (size_t)(n0 + lr) * K + lk;

    for (int k0 = 0; k0 < K; k0 += 16) {
#pragma unroll
        for (int s2 = 0; s2 < 2; s2++) {
            const int r = lr + (s2 << 6);
            float4 va = *(const float4*)(Ap + (size_t)(s2 << 6) * K + k0);
            As[(lk + 0) * 132 + r] = va.x;
            As[(lk + 1) * 132 + r] = va.y;
            As[(lk + 2) * 132 + r] = va.z;
            As[(lk + 3) * 132 + r] = va.w;
            float4 vw = *(const float4*)(Wp + (size_t)(s2 << 6) * K + k0);
            Ws[(lk + 0) * 132 + r] = vw.x;
            Ws[(lk + 1) * 132 + r] = vw.y;
            Ws[(lk + 2) * 132 + r] = vw.z;
            Ws[(lk + 3) * 132 + r] = vw.w;
        }
        __syncthreads();

#pragma unroll
        for (int kk = 0; kk < 16; kk++) {
            float4 a0 = *(const float4*)&As[kk * 132 + ty * 8];
            float4 a1 = *(const float4*)&As[kk * 132 + ty * 8 + 4];
            float4 b0 = *(const float4*)&Ws[kk * 132 + tx * 8];
            float4 b1 = *(const float4*)&Ws[kk * 132 + tx * 8 + 4];
            float a[8] = {a0.x, a0.y, a0.z, a0.w, a1.x, a1.y, a1.z, a1.w};
            float b[8] = {b0.x, b0.y, b0.z, b0.w, b1.x, b1.y, b1.z, b1.w};
#pragma unroll
            for (int i = 0; i < 8; i++)
#pragma unroll
                for (int j = 0; j < 8; j++)
                    acc[i][j] = fmaf(a[i], b[j], acc[i][j]);
        }
        __syncthreads();
    }

    float bb[8];
#pragma unroll
    for (int j = 0; j < 8; j++) bb[j] = bias[n0 + tx * 8 + j];
#pragma unroll
    for (int i = 0; i < 8; i++) {
        const size_t row = (size_t)(m0 + ty * 8 + i);
        float4 o0 = make_float4(acc[i][0] + bb[0], acc[i][1] + bb[1],
                                acc[i][2] + bb[2], acc[i][3] + bb[3]);
        float4 o1 = make_float4(acc[i][4] + bb[4], acc[i][5] + bb[5],
                                acc[i][6] + bb[6], acc[i][7] + bb[7]);
        *(float4*)&C[row * N + n0 + tx * 8]     = o0;
        *(float4*)&C[row * N + n0 + tx * 8 + 4] = o1;
    }
}

// ---------------------------------------------------------------------------
// Flash attention (causal), fp32. One CTA = (64 queries, one head, one batch).
// BLOCK_Q=64, BLOCK_K=64, HD=128, 256 threads (16x16), streaming softmax.
// smem: sQt[128][68] (Q^T, scaled)   sKt[128][64] (K^T, rotated cols)
//       sVs[64][132]                 sPt[64][68] (P^T)
// ---------------------------------------------------------------------------
#define ATTN_SMEM_FLOATS (128*68 + 128*64 + 64*132 + 64*68)
#define ATTN_SMEM_BYTES  (ATTN_SMEM_FLOATS * 4)

__global__ __launch_bounds__(256) void attn_kernel(
    const float* __restrict__ Q, const float* __restrict__ Kg,
    const float* __restrict__ Vg, float* __restrict__ Out)
{
    extern __shared__ float sm[];
    float* sQt = sm;                    // [128][68]
    float* sKt = sQt + 128 * 68;        // [128][64], col rotation (r + (d&60)) & 63
    float* sVs = sKt + 128 * 64;        // [64][132]
    float* sPt = sVs + 64 * 132;        // [64][68]

    const int tid = threadIdx.x;
    const int tx = tid & 15;
    const int ty = tid >> 4;
    const int qb = blockIdx.x;
    const int h  = blockIdx.y;
    const int b  = blockIdx.z;
    const int qg0 = qb << 6;
    const size_t tok0 = (size_t)b * T_SEQ;
    const float scale = 0.08838834764831845f;   // 1/sqrt(128)

    // Load Q tile transposed + pre-scaled
#pragma unroll
    for (int i = 0; i < 8; i++) {
        const int idx = tid + (i << 8);
        const int r  = idx >> 5;           // 0..63
        const int d4 = (idx & 31) << 2;    // 0..124
        float4 v = *(const float4*)&Q[(tok0 + qg0 + r) * D_MODEL + h * H_DIM + d4];
        sQt[(d4 + 0) * 68 + r] = v.x * scale;
        sQt[(d4 + 1) * 68 + r] = v.y * scale;
        sQt[(d4 + 2) * 68 + r] = v.z * scale;
        sQt[(d4 + 3) * 68 + r] = v.w * scale;
    }

    float o[4][8];
    float m_run[4], l_run[4];
#pragma unroll
    for (int i = 0; i < 4; i++) {
        m_run[i] = -INFINITY;
        l_run[i] = 0.0f;
#pragma unroll
        for (int u = 0; u < 8; u++) o[i][u] = 0.0f;
    }

    for (int kb = 0; kb <= qb; kb++) {
        __syncthreads();   // previous iter's PV reads of sVs/sPt done; sQt ready (iter 0)

        const size_t kt0 = tok0 + (size_t)(kb << 6);
#pragma unroll
        for (int i = 0; i < 8; i++) {
            const int idx = tid + (i << 8);
            const int r  = idx >> 5;
            const int d4 = (idx & 31) << 2;
            float4 kv = *(const float4*)&Kg[(kt0 + r) * H_DIM + d4];
            const int col = (r + (d4 & 60)) & 63;
            sKt[(d4 + 0) * 64 + col] = kv.x;
            sKt[(d4 + 1) * 64 + col] = kv.y;
            sKt[(d4 + 2) * 64 + col] = kv.z;
            sKt[(d4 + 3) * 64 + col] = kv.w;
            float4 vv = *(const float4*)&Vg[(kt0 + r) * H_DIM + d4];
            *(float4*)&sVs[r * 132 + d4] = vv;
        }
        __syncthreads();

        // S = (Q*scale) @ K^T   (64x64, each thread 4x4)
        float s[4][4];
#pragma unroll
        for (int i = 0; i < 4; i++)
#pragma unroll
            for (int j = 0; j < 4; j++) s[i][j] = 0.0f;

#pragma unroll 8
        for (int d = 0; d < 128; d++) {
            float4 a4 = *(const float4*)&sQt[d * 68 + ty * 4];
            float4 b4 = *(const float4*)&sKt[d * 64 + ((tx * 4 + (d & 60)) & 63)];
            float a[4] = {a4.x, a4.y, a4.z, a4.w};
            float bq[4] = {b4.x, b4.y, b4.z, b4.w};
#pragma unroll
            for (int i = 0; i < 4; i++)
#pragma unroll
                for (int j = 0; j < 4; j++)
                    s[i][j] = fmaf(a[i], bq[j], s[i][j]);
        }

        // Causal mask on the diagonal block only
        if (kb == qb) {
#pragma unroll
            for (int i = 0; i < 4; i++) {
                const int qg = qg0 + ty * 4 + i;
#pragma unroll
                for (int j = 0; j < 4; j++) {
                    const int kg = (kb << 6) + tx * 4 + j;
                    if (kg > qg) s[i][j] = -INFINITY;
                }
            }
        }

        // Streaming softmax; row groups live on 16-lane segments (same ty)
#pragma unroll
        for (int i = 0; i < 4; i++) {
            float mloc = fmaxf(fmaxf(s[i][0], s[i][1]), fmaxf(s[i][2], s[i][3]));
#pragma unroll
            for (int off = 1; off < 16; off <<= 1)
                mloc = fmaxf(mloc, __shfl_xor_sync(0xffffffffu, mloc, off, 16));
            const float m_new = fmaxf(m_run[i], mloc);
            const float alpha = __expf(m_run[i] - m_new);
            m_run[i] = m_new;

            const float p0 = __expf(s[i][0] - m_new);
            const float p1 = __expf(s[i][1] - m_new);
            const float p2 = __expf(s[i][2] - m_new);
            const float p3 = __expf(s[i][3] - m_new);
            float lsum = p0 + p1 + p2 + p3;
#pragma unroll
            for (int off = 1; off < 16; off <<= 1)
                lsum += __shfl_xor_sync(0xffffffffu, lsum, off, 16);
            l_run[i] = l_run[i] * alpha + lsum;

            sPt[(tx * 4 + 0) * 68 + ty * 4 + i] = p0;
            sPt[(tx * 4 + 1) * 68 + ty * 4 + i] = p1;
            sPt[(tx * 4 + 2) * 68 + ty * 4 + i] = p2;
            sPt[(tx * 4 + 3) * 68 + ty * 4 + i] = p3;

#pragma unroll
            for (int u = 0; u < 8; u++) o[i][u] *= alpha;
        }
        __syncthreads();

        // O += P @ V   (64x128, each thread 4x8)
#pragma unroll 4
        for (int j = 0; j < 64; j++) {
            float4 p4 = *(const float4*)&sPt[j * 68 + ty * 4];
            float4 v0 = *(const float4*)&sVs[j * 132 + tx * 8];
            float4 v1 = *(const float4*)&sVs[j * 132 + tx * 8 + 4];
            float p[4] = {p4.x, p4.y, p4.z, p4.w};
            float v[8] = {v0.x, v0.y, v0.z, v0.w, v1.x, v1.y, v1.z, v1.w};
#pragma unroll
            for (int i = 0; i < 4; i++)
#pragma unroll
                for (int u = 0; u < 8; u++)
                    o[i][u] = fmaf(p[i], v[u], o[i][u]);
        }
    }

    // Normalize and write out: Out[(b,t), h*128 + c]
#pragma unroll
    for (int i = 0; i < 4; i++) {
        const float inv = 1.0f / l_run[i];
        const size_t row = tok0 + qg0 + ty * 4 + i;
        float4 o0 = make_float4(o[i][0] * inv, o[i][1] * inv, o[i][2] * inv, o[i][3] * inv);
        float4 o1 = make_float4(o[i][4] * inv, o[i][5] * inv, o[i][6] * inv, o[i][7] * inv);
        *(float4*)&Out[row * D_MODEL + h * H_DIM + tx * 8]     = o0;
        *(float4*)&Out[row * D_MODEL + h * H_DIM + tx * 8 + 4] = o1;
    }
}

// ---------------------------------------------------------------------------
extern "C" void kernel_launch(void* const* d_in, const int* in_sizes, int n_in,
                              void* d_out, int out_size)
{
    const float* x    = (const float*)d_in[0];
    const float* wq_w = (const float*)d_in[1];
    const float* wq_b = (const float*)d_in[2];
    const float* wk_w = (const float*)d_in[3];
    const float* wk_b = (const float*)d_in[4];
    const float* wv_w = (const float*)d_in[5];
    const float* wv_b = (const float*)d_in[6];
    const float* wo_w = (const float*)d_in[7];
    const float* wo_b = (const float*)d_in[8];
    float* out = (float*)d_out;

    float *qp, *kp, *vp, *ap;
    cudaGetSymbolAddress((void**)&qp, g_q);
    cudaGetSymbolAddress((void**)&kp, g_k);
    cudaGetSymbolAddress((void**)&vp, g_v);
    cudaGetSymbolAddress((void**)&ap, g_attn);

    const dim3 blk(256);

    // QKV projections
    sgemm_bias_kernel<<<dim3(D_MODEL / 128, N_TOK / 128), blk>>>(
        x, wq_w, wq_b, qp, N_TOK, D_MODEL, D_MODEL);
    sgemm_bias_kernel<<<dim3(1, N_TOK / 128), blk>>>(
        x, wk_w, wk_b, kp, N_TOK, H_DIM, D_MODEL);
    sgemm_bias_kernel<<<dim3(1, N_TOK / 128), blk>>>(
        x, wv_w, wv_b, vp, N_TOK, H_DIM, D_MODEL);

    // Causal flash attention
    cudaFuncSetAttribute(attn_kernel, cudaFuncAttributeMaxDynamicSharedMemorySize,
                         ATTN_SMEM_BYTES);
    attn_kernel<<<dim3(T_SEQ / 64, N_HEAD, 2), blk, ATTN_SMEM_BYTES>>>(qp, kp, vp, ap);

    // Output projection
    sgemm_bias_kernel<<<dim3(D_MODEL / 128, N_TOK / 128), blk>>>(
        ap, wo_w, wo_b, out, N_TOK, D_MODEL, D_MODEL);
}

// round 3
// speedup vs baseline: 1.9190x; 1.9190x over previous
#include <cuda_runtime.h>
#include <math.h>
#include <stdint.h>

#define D_MODEL 4096
#define N_TOK   4096   // B*T
#define T_SEQ   2048
#define N_HEAD  32
#define H_DIM   128

// Scratch (allocation-free rule: __device__ globals)
__device__ float g_q[(size_t)N_TOK * D_MODEL];
__device__ float g_k[(size_t)N_TOK * H_DIM];
__device__ float g_v[(size_t)N_TOK * H_DIM];
__device__ float g_attn[(size_t)N_TOK * D_MODEL];

__device__ __forceinline__ uint32_t f2tf32(float x) {
    uint32_t r;
    asm("cvt.rna.tf32.f32 %0, %1;" : "=r"(r) : "f"(x));
    return r;
}

// ---------------------------------------------------------------------------
// TF32 tensor-core GEMM: C[M,N] = A[M,K] @ W[N,K]^T + bias[N]
// BM=128, BN=128, BK=32. 256 threads = 8 warps, each warp a 64x32 tile of C
// via mma.sync.m16n8k8.tf32. Double-buffered smem, [row][k] stride-36 layout
// (conflict-free fragment loads; tf32 rounding applied at staging).
// ---------------------------------------------------------------------------
#define BM 128
#define BN 128
#define BK 32
#define SSTR 36   // smem row stride in floats
#define GEMM_SMEM_BYTES (2 * (BM * SSTR + BN * SSTR) * 4)

__global__ __launch_bounds__(256) void gemm_tf32_kernel(
    const float* __restrict__ A, const float* __restrict__ W,
    const float* __restrict__ bias, float* __restrict__ C,
    int M, int N, int K)
{
    extern __shared__ float sm[];
    // buffer b: As = sm + b*(BM+BN)*SSTR ; Ws = As + BM*SSTR
    const int tid = threadIdx.x;
    const int w   = tid >> 5;
    const int l   = tid & 31;
    const int g   = l >> 2;     // 0..7
    const int t4  = l & 3;      // 0..3
    const int m0  = blockIdx.y * BM;
    const int n0  = blockIdx.x * BN;

    // staging map: per warp-iter: row = w*4 + (l>>3) + it*32, k4 = (l&7)*4
    const int srow = w * 4 + (l >> 3);
    const int sk4  = (l & 7) * 4;

    const float* Ap = A + (size_t)(m0 + srow) * K + sk4;
    const float* Wp = W + (size_t)(n0 + srow) * K + sk4;

    // warp tile origin
    const int mw = (w >> 2) * 64;   // 0 or 64
    const int nw = (w & 3) * 32;    // 0,32,64,96

    float acc[4][4][4];
#pragma unroll
    for (int i = 0; i < 4; i++)
#pragma unroll
        for (int j = 0; j < 4; j++)
#pragma unroll
            for (int c = 0; c < 4; c++) acc[i][j][c] = 0.0f;

    float4 ra[4], rb[4];

    // prologue: stage tile 0
#pragma unroll
    for (int it = 0; it < 4; it++) {
        ra[it] = *(const float4*)(Ap + (size_t)(it * 32) * K);
        rb[it] = *(const float4*)(Wp + (size_t)(it * 32) * K);
    }
    {
        float* As = sm;
        float* Ws = sm + BM * SSTR;
#pragma unroll
        for (int it = 0; it < 4; it++) {
            float4 ta, tb;
            ta.x = __uint_as_float(f2tf32(ra[it].x));
            ta.y = __uint_as_float(f2tf32(ra[it].y));
            ta.z = __uint_as_float(f2tf32(ra[it].z));
            ta.w = __uint_as_float(f2tf32(ra[it].w));
            *(float4*)&As[(srow + it * 32) * SSTR + sk4] = ta;
            tb.x = __uint_as_float(f2tf32(rb[it].x));
            tb.y = __uint_as_float(f2tf32(rb[it].y));
            tb.z = __uint_as_float(f2tf32(rb[it].z));
            tb.w = __uint_as_float(f2tf32(rb[it].w));
            *(float4*)&Ws[(srow + it * 32) * SSTR + sk4] = tb;
        }
    }
    __syncthreads();

    const int NT = K / BK;
#pragma unroll 1
    for (int kt = 0; kt < NT; kt++) {
        // prefetch next tile into registers
        if (kt + 1 < NT) {
#pragma unroll
            for (int it = 0; it < 4; it++) {
                ra[it] = *(const float4*)(Ap + (size_t)(it * 32) * K + (kt + 1) * BK);
                rb[it] = *(const float4*)(Wp + (size_t)(it * 32) * K + (kt + 1) * BK);
            }
        }

        const float* As = sm + (kt & 1) * (BM + BN) * SSTR;
        const float* Ws = As + BM * SSTR;

#pragma unroll
        for (int ks = 0; ks < 4; ks++) {
            const int kk = ks * 8;
            uint32_t af[4][4], bf[4][2];
#pragma unroll
            for (int i = 0; i < 4; i++) {
                const float* p = &As[(mw + 16 * i + g) * SSTR + kk + t4];
                af[i][0] = __float_as_uint(p[0]);
                af[i][1] = __float_as_uint(p[8 * SSTR]);
                af[i][2] = __float_as_uint(p[4]);
                af[i][3] = __float_as_uint(p[8 * SSTR + 4]);
            }
#pragma unroll
            for (int j = 0; j < 4; j++) {
                const float* p = &Ws[(nw + 8 * j + g) * SSTR + kk + t4];
                bf[j][0] = __float_as_uint(p[0]);
                bf[j][1] = __float_as_uint(p[4]);
            }
#pragma unroll
            for (int i = 0; i < 4; i++)
#pragma unroll
                for (int j = 0; j < 4; j++) {
                    asm volatile(
                        "mma.sync.aligned.m16n8k8.row.col.f32.tf32.tf32.f32 "
                        "{%0,%1,%2,%3}, {%4,%5,%6,%7}, {%8,%9}, {%0,%1,%2,%3};\n"
                        : "+f"(acc[i][j][0]), "+f"(acc[i][j][1]),
                          "+f"(acc[i][j][2]), "+f"(acc[i][j][3])
                        : "r"(af[i][0]), "r"(af[i][1]), "r"(af[i][2]), "r"(af[i][3]),
                          "r"(bf[j][0]), "r"(bf[j][1]));
                }
        }

        // stage next tile into the other buffer
        if (kt + 1 < NT) {
            float* Asn = sm + ((kt + 1) & 1) * (BM + BN) * SSTR;
            float* Wsn = Asn + BM * SSTR;
#pragma unroll
            for (int it = 0; it < 4; it++) {
                float4 ta, tb;
                ta.x = __uint_as_float(f2tf32(ra[it].x));
                ta.y = __uint_as_float(f2tf32(ra[it].y));
                ta.z = __uint_as_float(f2tf32(ra[it].z));
                ta.w = __uint_as_float(f2tf32(ra[it].w));
                *(float4*)&Asn[(srow + it * 32) * SSTR + sk4] = ta;
                tb.x = __uint_as_float(f2tf32(rb[it].x));
                tb.y = __uint_as_float(f2tf32(rb[it].y));
                tb.z = __uint_as_float(f2tf32(rb[it].z));
                tb.w = __uint_as_float(f2tf32(rb[it].w));
                *(float4*)&Wsn[(srow + it * 32) * SSTR + sk4] = tb;
            }
        }
        __syncthreads();
    }

    // epilogue: bias + store (float2 per fragment row)
#pragma unroll
    for (int i = 0; i < 4; i++) {
#pragma unroll
        for (int j = 0; j < 4; j++) {
            const int row = m0 + mw + 16 * i + g;
            const int col = n0 + nw + 8 * j + t4 * 2;
            const float b0 = bias[col], b1 = bias[col + 1];
            float2 v0 = make_float2(acc[i][j][0] + b0, acc[i][j][1] + b1);
            float2 v1 = make_float2(acc[i][j][2] + b0, acc[i][j][3] + b1);
            *(float2*)&C[(size_t)row * N + col]       = v0;
            *(float2*)&C[(size_t)(row + 8) * N + col] = v1;
        }
    }
}

// ---------------------------------------------------------------------------
// Flash attention (causal), fp32. One CTA = (64 queries, one head, one batch).
// BLOCK_Q=64, BLOCK_K=64, HD=128, 256 threads (16x16), streaming softmax.
// ---------------------------------------------------------------------------
#define ATTN_SMEM_FLOATS (128*68 + 128*64 + 64*132 + 64*68)
#define ATTN_SMEM_BYTES  (ATTN_SMEM_FLOATS * 4)

__global__ __launch_bounds__(256) void attn_kernel(
    const float* __restrict__ Q, const float* __restrict__ Kg,
    const float* __restrict__ Vg, float* __restrict__ Out)
{
    extern __shared__ float sm[];
    float* sQt = sm;                    // [128][68]
    float* sKt = sQt + 128 * 68;        // [128][64], col rotation (r + (d&60)) & 63
    float* sVs = sKt + 128 * 64;        // [64][132]
    float* sPt = sVs + 64 * 132;        // [64][68]

    const int tid = threadIdx.x;
    const int tx = tid & 15;
    const int ty = tid >> 4;
    const int qb = blockIdx.x;
    const int h  = blockIdx.y;
    const int b  = blockIdx.z;
    const int qg0 = qb << 6;
    const size_t tok0 = (size_t)b * T_SEQ;
    const float scale = 0.08838834764831845f;   // 1/sqrt(128)

#pragma unroll
    for (int i = 0; i < 8; i++) {
        const int idx = tid + (i << 8);
        const int r  = idx >> 5;
        const int d4 = (idx & 31) << 2;
        float4 v = *(const float4*)&Q[(tok0 + qg0 + r) * D_MODEL + h * H_DIM + d4];
        sQt[(d4 + 0) * 68 + r] = v.x * scale;
        sQt[(d4 + 1) * 68 + r] = v.y * scale;
        sQt[(d4 + 2) * 68 + r] = v.z * scale;
        sQt[(d4 + 3) * 68 + r] = v.w * scale;
    }

    float o[4][8];
    float m_run[4], l_run[4];
#pragma unroll
    for (int i = 0; i < 4; i++) {
        m_run[i] = -INFINITY;
        l_run[i] = 0.0f;
#pragma unroll
        for (int u = 0; u < 8; u++) o[i][u] = 0.0f;
    }

    for (int kb = 0; kb <= qb; kb++) {
        __syncthreads();

        const size_t kt0 = tok0 + (size_t)(kb << 6);
#pragma unroll
        for (int i = 0; i < 8; i++) {
            const int idx = tid + (i << 8);
            const int r  = idx >> 5;
            const int d4 = (idx & 31) << 2;
            float4 kv = *(const float4*)&Kg[(kt0 + r) * H_DIM + d4];
            const int col = (r + (d4 & 60)) & 63;
            sKt[(d4 + 0) * 64 + col] = kv.x;
            sKt[(d4 + 1) * 64 + col] = kv.y;
            sKt[(d4 + 2) * 64 + col] = kv.z;
            sKt[(d4 + 3) * 64 + col] = kv.w;
            float4 vv = *(const float4*)&Vg[(kt0 + r) * H_DIM + d4];
            *(float4*)&sVs[r * 132 + d4] = vv;
        }
        __syncthreads();

        float s[4][4];
#pragma unroll
        for (int i = 0; i < 4; i++)
#pragma unroll
            for (int j = 0; j < 4; j++) s[i][j] = 0.0f;

#pragma unroll 8
        for (int d = 0; d < 128; d++) {
            float4 a4 = *(const float4*)&sQt[d * 68 + ty * 4];
            float4 b4 = *(const float4*)&sKt[d * 64 + ((tx * 4 + (d & 60)) & 63)];
            float a[4] = {a4.x, a4.y, a4.z, a4.w};
            float bq[4] = {b4.x, b4.y, b4.z, b4.w};
#pragma unroll
            for (int i = 0; i < 4; i++)
#pragma unroll
                for (int j = 0; j < 4; j++)
                    s[i][j] = fmaf(a[i], bq[j], s[i][j]);
        }

        if (kb == qb) {
#pragma unroll
            for (int i = 0; i < 4; i++) {
                const int qg = qg0 + ty * 4 + i;
#pragma unroll
                for (int j = 0; j < 4; j++) {
                    const int kg = (kb << 6) + tx * 4 + j;
                    if (kg > qg) s[i][j] = -INFINITY;
                }
            }
        }

#pragma unroll
        for (int i = 0; i < 4; i++) {
            float mloc = fmaxf(fmaxf(s[i][0], s[i][1]), fmaxf(s[i][2], s[i][3]));
#pragma unroll
            for (int off = 1; off < 16; off <<= 1)
                mloc = fmaxf(mloc, __shfl_xor_sync(0xffffffffu, mloc, off, 16));
            const float m_new = fmaxf(m_run[i], mloc);
            const float alpha = __expf(m_run[i] - m_new);
            m_run[i] = m_new;

            const float p0 = __expf(s[i][0] - m_new);
            const float p1 = __expf(s[i][1] - m_new);
            const float p2 = __expf(s[i][2] - m_new);
            const float p3 = __expf(s[i][3] - m_new);
            float lsum = p0 + p1 + p2 + p3;
#pragma unroll
            for (int off = 1; off < 16; off <<= 1)
                lsum += __shfl_xor_sync(0xffffffffu, lsum, off, 16);
            l_run[i] = l_run[i] * alpha + lsum;

            sPt[(tx * 4 + 0) * 68 + ty * 4 + i] = p0;
            sPt[(tx * 4 + 1) * 68 + ty * 4 + i] = p1;
            sPt[(tx * 4 + 2) * 68 + ty * 4 + i] = p2;
            sPt[(tx * 4 + 3) * 68 + ty * 4 + i] = p3;

#pragma unroll
            for (int u = 0; u < 8; u++) o[i][u] *= alpha;
        }
        __syncthreads();

#pragma unroll 4
        for (int j = 0; j < 64; j++) {
            float4 p4 = *(const float4*)&sPt[j * 68 + ty * 4];
            float4 v0 = *(const float4*)&sVs[j * 132 + tx * 8];
            float4 v1 = *(const float4*)&sVs[j * 132 + tx * 8 + 4];
            float p[4] = {p4.x, p4.y, p4.z, p4.w};
            float v[8] = {v0.x, v0.y, v0.z, v0.w, v1.x, v1.y, v1.z, v1.w};
#pragma unroll
            for (int i = 0; i < 4; i++)
#pragma unroll
                for (int u = 0; u < 8; u++)
                    o[i][u] = fmaf(p[i], v[u], o[i][u]);
        }
    }

#pragma unroll
    for (int i = 0; i < 4; i++) {
        const float inv = 1.0f / l_run[i];
        const size_t row = tok0 + qg0 + ty * 4 + i;
        float4 o0 = make_float4(o[i][0] * inv, o[i][1] * inv, o[i][2] * inv, o[i][3] * inv);
        float4 o1 = make_float4(o[i][4] * inv, o[i][5] * inv, o[i][6] * inv, o[i][7] * inv);
        *(float4*)&Out[row * D_MODEL + h * H_DIM + tx * 8]     = o0;
        *(float4*)&Out[row * D_MODEL + h * H_DIM + tx * 8 + 4] = o1;
    }
}

// ---------------------------------------------------------------------------
extern "C" void kernel_launch(void* const* d_in, const int* in_sizes, int n_in,
                              void* d_out, int out_size)
{
    const float* x    = (const float*)d_in[0];
    const float* wq_w = (const float*)d_in[1];
    const float* wq_b = (const float*)d_in[2];
    const float* wk_w = (const float*)d_in[3];
    const float* wk_b = (const float*)d_in[4];
    const float* wv_w = (const float*)d_in[5];
    const float* wv_b = (const float*)d_in[6];
    const float* wo_w = (const float*)d_in[7];
    const float* wo_b = (const float*)d_in[8];
    float* out = (float*)d_out;

    float *qp, *kp, *vp, *ap;
    cudaGetSymbolAddress((void**)&qp, g_q);
    cudaGetSymbolAddress((void**)&kp, g_k);
    cudaGetSymbolAddress((void**)&vp, g_v);
    cudaGetSymbolAddress((void**)&ap, g_attn);

    const dim3 blk(256);

    cudaFuncSetAttribute(gemm_tf32_kernel, cudaFuncAttributeMaxDynamicSharedMemorySize,
                         GEMM_SMEM_BYTES);
    cudaFuncSetAttribute(attn_kernel, cudaFuncAttributeMaxDynamicSharedMemorySize,
                         ATTN_SMEM_BYTES);

    // QKV projections (tf32 tensor cores)
    gemm_tf32_kernel<<<dim3(D_MODEL / BN, N_TOK / BM), blk, GEMM_SMEM_BYTES>>>(
        x, wq_w, wq_b, qp, N_TOK, D_MODEL, D_MODEL);
    gemm_tf32_kernel<<<dim3(H_DIM / BN, N_TOK / BM), blk, GEMM_SMEM_BYTES>>>(
        x, wk_w, wk_b, kp, N_TOK, H_DIM, D_MODEL);
    gemm_tf32_kernel<<<dim3(H_DIM / BN, N_TOK / BM), blk, GEMM_SMEM_BYTES>>>(
        x, wv_w, wv_b, vp, N_TOK, H_DIM, D_MODEL);

    // Causal flash attention (fp32)
    attn_kernel<<<dim3(T_SEQ / 64, N_HEAD, 2), blk, ATTN_SMEM_BYTES>>>(qp, kp, vp, ap);

    // Output projection
    gemm_tf32_kernel<<<dim3(D_MODEL / BN, N_TOK / BM), blk, GEMM_SMEM_BYTES>>>(
        ap, wo_w, wo_b, out, N_TOK, D_MODEL, D_MODEL);
}

// round 5
// speedup vs baseline: 8.7023x; 4.5347x over previous
#include <cuda_runtime.h>
#include <cuda_fp16.h>
#include <math.h>
#include <stdint.h>

#define D_MODEL 4096
#define N_TOK   4096   // B*T
#define T_SEQ   2048
#define N_HEAD  32
#define H_DIM   128

// ---------------------------------------------------------------------------
// Scratch (allocation-free rule: __device__ globals)
// ---------------------------------------------------------------------------
__device__ __half g_xh [(size_t)N_TOK * D_MODEL];
__device__ __half g_wqh[(size_t)D_MODEL * D_MODEL];
__device__ __half g_wkh[(size_t)H_DIM * D_MODEL];
__device__ __half g_wvh[(size_t)H_DIM * D_MODEL];
__device__ __half g_woh[(size_t)D_MODEL * D_MODEL];
__device__ __half g_qh [(size_t)N_TOK * D_MODEL];
__device__ __half g_kh [(size_t)N_TOK * H_DIM];
__device__ __half g_vh [(size_t)N_TOK * H_DIM];
__device__ __half g_ah [(size_t)N_TOK * D_MODEL];

// ---------------------------------------------------------------------------
// PTX helpers (base sm_103 feature set only: cp.async / ldmatrix / mma.sync)
// ---------------------------------------------------------------------------
__device__ __forceinline__ uint32_t smem_u32(const void* p) {
    uint32_t a;
    asm("{ .reg .u64 t; cvta.to.shared.u64 t, %1; cvt.u32.u64 %0, t; }"
        : "=r"(a) : "l"(p));
    return a;
}

#define CP_ASYNC16(saddr, gptr) \
    asm volatile("cp.async.cg.shared.global [%0], [%1], 16;" \
                 :: "r"(saddr), "l"(gptr))
#define CP_COMMIT()  asm volatile("cp.async.commit_group;" ::: "memory")
#define CP_WAIT(n)   asm volatile("cp.async.wait_group %0;" :: "n"(n) : "memory")

#define LDSM_X4(r0, r1, r2, r3, addr) \
    asm volatile("ldmatrix.sync.aligned.m8n8.x4.shared.b16 {%0,%1,%2,%3}, [%4];" \
                 : "=r"(r0), "=r"(r1), "=r"(r2), "=r"(r3) : "r"(addr))
#define LDSM_X4_T(r0, r1, r2, r3, addr) \
    asm volatile("ldmatrix.sync.aligned.m8n8.x4.trans.shared.b16 {%0,%1,%2,%3}, [%4];" \
                 : "=r"(r0), "=r"(r1), "=r"(r2), "=r"(r3) : "r"(addr))

#define MMA16816(d, a0, a1, a2, a3, b0, b1) \
    asm volatile("mma.sync.aligned.m16n8k16.row.col.f32.f16.f16.f32 " \
                 "{%0,%1,%2,%3}, {%4,%5,%6,%7}, {%8,%9}, {%0,%1,%2,%3};" \
                 : "+f"((d)[0]), "+f"((d)[1]), "+f"((d)[2]), "+f"((d)[3]) \
                 : "r"(a0), "r"(a1), "r"(a2), "r"(a3), "r"(b0), "r"(b1))

__device__ __forceinline__ uint32_t h2u(__half2 h) {
    return *reinterpret_cast<uint32_t*>(&h);
}

// ---------------------------------------------------------------------------
// fp32 -> fp16 convert (vectorized)
// ---------------------------------------------------------------------------
__global__ void cvt_kernel(const float* __restrict__ in, __half* __restrict__ out,
                           int n) {
    int i = (blockIdx.x * blockDim.x + threadIdx.x) * 4;
    if (i < n) {
        float4 f = *(const float4*)(in + i);
        __half2 h0 = __floats2half2_rn(f.x, f.y);
        __half2 h1 = __floats2half2_rn(f.z, f.w);
        *(uint2*)(out + i) = make_uint2(h2u(h0), h2u(h1));
    }
}

// ---------------------------------------------------------------------------
// fp16 tensor-core GEMM: C[M,N] = A[M,K] @ W[N,K]^T + bias
// BM=BN=128, BK=64, 256 thr / 8 warps (warp tile 64x32), 3-stage cp.async,
// XOR-swizzled smem ([row][128B], chunk ^= row&7), ldmatrix fragments.
// ---------------------------------------------------------------------------
#define GSTAGES 3
#define GEMM_SMEM (GSTAGES * 32768)

template<typename OutT>
__device__ __forceinline__ void st2(OutT* C, size_t off, float v0, float v1);
template<> __device__ __forceinline__ void st2<__half>(__half* C, size_t off,
                                                       float v0, float v1) {
    *reinterpret_cast<__half2*>(C + off) = __floats2half2_rn(v0, v1);
}
template<> __device__ __forceinline__ void st2<float>(float* C, size_t off,
                                                      float v0, float v1) {
    *reinterpret_cast<float2*>(C + off) = make_float2(v0, v1);
}

template<typename OutT>
__global__ __launch_bounds__(256) void gemm_h_kernel(
    const __half* __restrict__ A, const __half* __restrict__ W,
    const float* __restrict__ bias, OutT* __restrict__ C,
    int M, int N, int K)
{
    extern __shared__ char smc[];
    const uint32_t sb = smem_u32(smc);
    const int tid = threadIdx.x;
    const int l = tid & 31, w = tid >> 5;
    const int m0 = blockIdx.y * 128, n0 = blockIdx.x * 128;
    const int wm = (w >> 2) * 64, wn = (w & 3) * 32;

    const int sr = tid >> 3;   // 0..31
    const int sc = tid & 7;    // chunk 0..7
    const __half* Ag = A + (size_t)(m0 + sr) * K + sc * 8;
    const __half* Wg = W + (size_t)(n0 + sr) * K + sc * 8;

    const int NT = K / 64;

    auto stage = [&](int kt) {
        const int st = kt % GSTAGES;
        const uint32_t ab = sb + st * 32768;
        const uint32_t bb = ab + 16384;
        const int k0 = kt * 64;
#pragma unroll
        for (int it = 0; it < 4; it++) {
            const int r = sr + it * 32;
            const uint32_t soff = (uint32_t)(r * 128 + ((sc ^ (r & 7)) * 16));
            CP_ASYNC16(ab + soff, Ag + (size_t)(it * 32) * K + k0);
            CP_ASYNC16(bb + soff, Wg + (size_t)(it * 32) * K + k0);
        }
    };

    float acc[4][4][4];
#pragma unroll
    for (int i = 0; i < 4; i++)
#pragma unroll
        for (int j = 0; j < 4; j++)
#pragma unroll
            for (int c = 0; c < 4; c++) acc[i][j][c] = 0.0f;

    stage(0); CP_COMMIT();
    stage(1); CP_COMMIT();

#pragma unroll 1
    for (int kt = 0; kt < NT; kt++) {
        if (kt + 2 < NT) { stage(kt + 2); CP_COMMIT(); CP_WAIT(2); }
        else if (kt + 1 < NT) { CP_WAIT(1); }
        else { CP_WAIT(0); }
        __syncthreads();

        const int st = kt % GSTAGES;
        const uint32_t ab = sb + st * 32768;
        const uint32_t bb = ab + 16384;

#pragma unroll
        for (int ks = 0; ks < 4; ks++) {
            uint32_t a[4][4], b[4][2];
#pragma unroll
            for (int i = 0; i < 4; i++) {
                const int row = wm + i * 16 + (l & 15);
                const int ch = ks * 2 + (l >> 4);
                LDSM_X4(a[i][0], a[i][1], a[i][2], a[i][3],
                        ab + row * 128 + ((ch ^ (row & 7)) * 16));
            }
#pragma unroll
            for (int jj = 0; jj < 2; jj++) {
                const int nrow = wn + jj * 16 + (l & 7) + ((l >> 4) & 1) * 8;
                const int ch = ks * 2 + ((l >> 3) & 1);
                LDSM_X4(b[jj * 2][0], b[jj * 2][1], b[jj * 2 + 1][0], b[jj * 2 + 1][1],
                        bb + nrow * 128 + ((ch ^ (nrow & 7)) * 16));
            }
#pragma unroll
            for (int i = 0; i < 4; i++)
#pragma unroll
                for (int j = 0; j < 4; j++)
                    MMA16816(acc[i][j], a[i][0], a[i][1], a[i][2], a[i][3],
                             b[j][0], b[j][1]);
        }
        __syncthreads();
    }

    // epilogue: bias + store
#pragma unroll
    for (int i = 0; i < 4; i++) {
#pragma unroll
        for (int j = 0; j < 4; j++) {
            const int row = m0 + wm + i * 16 + (l >> 2);
            const int col = n0 + wn + j * 8 + (l & 3) * 2;
            const float b0 = bias[col], b1 = bias[col + 1];
            st2<OutT>(C, (size_t)row * N + col, acc[i][j][0] + b0, acc[i][j][1] + b1);
            st2<OutT>(C, (size_t)(row + 8) * N + col, acc[i][j][2] + b0, acc[i][j][3] + b1);
        }
    }
}

// ---------------------------------------------------------------------------
// Flash attention (causal), fp16 mma. CTA = 128 queries x one head x one batch.
// 8 warps, warp w owns q-rows 16w..16w+15. Key blocks of 64, double-buffered
// cp.async K/V. S=QK^T via mma (Q from smem ldmatrix, K via ldmatrix),
// fp32 softmax on fragments (4-lane shfl), P in registers -> PV mma with
// V via ldmatrix.trans. smem: Q 32KB + 2 x (K 16KB + V 16KB) = 96KB.
// ---------------------------------------------------------------------------
#define ATTN_SMEM (32768 + 2 * 32768)

__global__ __launch_bounds__(256) void attn_h_kernel(
    const __half* __restrict__ Qg, const __half* __restrict__ Kg,
    const __half* __restrict__ Vg, __half* __restrict__ Og)
{
    extern __shared__ char smc[];
    const uint32_t sb = smem_u32(smc);
    const int tid = threadIdx.x;
    const int l = tid & 31, w = tid >> 5;
    const int qb = blockIdx.x, h = blockIdx.y, b = blockIdx.z;
    const size_t tok0 = (size_t)b * T_SEQ;
    const float fscale = 0.08838834764831845f;   // 1/sqrt(128)

    // stage Q: 128 rows x 16 chunks (16B), swizzled
    {
#pragma unroll
        for (int it = 0; it < 8; it++) {
            const int idx = tid + it * 256;
            const int r = idx >> 4, ch = idx & 15;
            const __half* g = Qg + (tok0 + qb * 128 + r) * D_MODEL + h * H_DIM + ch * 8;
            CP_ASYNC16(sb + r * 256 + ((ch ^ (r & 7)) * 16), g);
        }
    }

    auto stage_kv = [&](int kb) {
        const uint32_t kbb = sb + 32768 + (kb & 1) * 32768;
        const uint32_t vbb = kbb + 16384;
#pragma unroll
        for (int it = 0; it < 4; it++) {
            const int idx = tid + it * 256;
            const int r = idx >> 4, ch = idx & 15;
            const uint32_t off = (uint32_t)(r * 256 + ((ch ^ (r & 7)) * 16));
            CP_ASYNC16(kbb + off, Kg + (tok0 + kb * 64 + r) * H_DIM + ch * 8);
            CP_ASYNC16(vbb + off, Vg + (tok0 + kb * 64 + r) * H_DIM + ch * 8);
        }
    };

    stage_kv(0); CP_COMMIT();

    float o[16][4];
#pragma unroll
    for (int jt = 0; jt < 16; jt++)
#pragma unroll
        for (int c = 0; c < 4; c++) o[jt][c] = 0.0f;
    float mA = -1e30f, mB = -1e30f, lA = 0.0f, lB = 0.0f;

    const int nb = 2 * qb + 2;
    const int rowA = qb * 128 + w * 16 + (l >> 2);   // global q row (frag row A)
    const int wmax = qb * 128 + w * 16 + 15;          // warp's max q row

#pragma unroll 1
    for (int kb = 0; kb < nb; kb++) {
        if (kb + 1 < nb) { stage_kv(kb + 1); CP_COMMIT(); CP_WAIT(1); }
        else { CP_WAIT(0); }
        __syncthreads();

        if (kb * 64 <= wmax) {   // warp has at least one unmasked key
            const uint32_t kbb = sb + 32768 + (kb & 1) * 32768;
            const uint32_t vbb = kbb + 16384;

            // ---- S = Q @ K^T (16 x 64 per warp) ----
            float s[8][4];
#pragma unroll
            for (int j = 0; j < 8; j++)
#pragma unroll
                for (int c = 0; c < 4; c++) s[j][c] = 0.0f;

#pragma unroll
            for (int ks = 0; ks < 8; ks++) {
                uint32_t a0, a1, a2, a3;
                {
                    const int row = w * 16 + (l & 15);
                    const int ch = ks * 2 + (l >> 4);
                    LDSM_X4(a0, a1, a2, a3, sb + row * 256 + ((ch ^ (row & 7)) * 16));
                }
                uint32_t bf[8][2];
#pragma unroll
                for (int jj = 0; jj < 4; jj++) {
                    const int nrow = jj * 16 + (l & 7) + ((l >> 4) & 1) * 8;
                    const int ch = ks * 2 + ((l >> 3) & 1);
                    LDSM_X4(bf[jj * 2][0], bf[jj * 2][1],
                            bf[jj * 2 + 1][0], bf[jj * 2 + 1][1],
                            kbb + nrow * 256 + ((ch ^ (nrow & 7)) * 16));
                }
#pragma unroll
                for (int j = 0; j < 8; j++)
                    MMA16816(s[j], a0, a1, a2, a3, bf[j][0], bf[j][1]);
            }

            // ---- causal mask (only blocks overlapping the diagonal) ----
            if (kb >= 2 * qb) {
#pragma unroll
                for (int j = 0; j < 8; j++) {
                    const int col = kb * 64 + j * 8 + (l & 3) * 2;
                    if (col > rowA)     s[j][0] = -1e30f;
                    if (col + 1 > rowA) s[j][1] = -1e30f;
                    if (col > rowA + 8)     s[j][2] = -1e30f;
                    if (col + 1 > rowA + 8) s[j][3] = -1e30f;
                }
            }

            // ---- streaming softmax (rows A = t>>2, B = +8) ----
            float mlA = -1e30f, mlB = -1e30f;
#pragma unroll
            for (int j = 0; j < 8; j++) {
                mlA = fmaxf(mlA, fmaxf(s[j][0], s[j][1]));
                mlB = fmaxf(mlB, fmaxf(s[j][2], s[j][3]));
            }
            mlA = fmaxf(mlA, __shfl_xor_sync(0xffffffffu, mlA, 1));
            mlA = fmaxf(mlA, __shfl_xor_sync(0xffffffffu, mlA, 2));
            mlB = fmaxf(mlB, __shfl_xor_sync(0xffffffffu, mlB, 1));
            mlB = fmaxf(mlB, __shfl_xor_sync(0xffffffffu, mlB, 2));

            const float mnA = fmaxf(mA, mlA), mnB = fmaxf(mB, mlB);
            const float aA = __expf((mA - mnA) * fscale);
            const float aB = __expf((mB - mnB) * fscale);
            mA = mnA; mB = mnB;

            uint32_t pA[8], pB[8];
            float sumA = 0.0f, sumB = 0.0f;
#pragma unroll
            for (int j = 0; j < 8; j++) {
                const float e0 = __expf((s[j][0] - mA) * fscale);
                const float e1 = __expf((s[j][1] - mA) * fscale);
                const float e2 = __expf((s[j][2] - mB) * fscale);
                const float e3 = __expf((s[j][3] - mB) * fscale);
                sumA += e0 + e1; sumB += e2 + e3;
                pA[j] = h2u(__floats2half2_rn(e0, e1));
                pB[j] = h2u(__floats2half2_rn(e2, e3));
            }
            sumA += __shfl_xor_sync(0xffffffffu, sumA, 1);
            sumA += __shfl_xor_sync(0xffffffffu, sumA, 2);
            sumB += __shfl_xor_sync(0xffffffffu, sumB, 1);
            sumB += __shfl_xor_sync(0xffffffffu, sumB, 2);
            lA = lA * aA + sumA;
            lB = lB * aB + sumB;

#pragma unroll
            for (int jt = 0; jt < 16; jt++) {
                o[jt][0] *= aA; o[jt][1] *= aA;
                o[jt][2] *= aB; o[jt][3] *= aB;
            }

            // ---- O += P @ V (P in registers, V via ldmatrix.trans) ----
#pragma unroll
            for (int ks2 = 0; ks2 < 4; ks2++) {
                const uint32_t pa0 = pA[2 * ks2],     pa1 = pB[2 * ks2];
                const uint32_t pa2 = pA[2 * ks2 + 1], pa3 = pB[2 * ks2 + 1];
                const int key = ks2 * 16 + (l & 7) + ((l >> 3) & 1) * 8;
#pragma unroll
                for (int u = 0; u < 8; u++) {
                    const int ch = 2 * u + (l >> 4);
                    uint32_t v0, v1, v2, v3;
                    LDSM_X4_T(v0, v1, v2, v3,
                              vbb + key * 256 + ((ch ^ (key & 7)) * 16));
                    MMA16816(o[2 * u],     pa0, pa1, pa2, pa3, v0, v1);
                    MMA16816(o[2 * u + 1], pa0, pa1, pa2, pa3, v2, v3);
                }
            }
        }
        __syncthreads();
    }

    // ---- normalize + write fp16 output ----
    const float invA = 1.0f / lA, invB = 1.0f / lB;
    const size_t rA = tok0 + qb * 128 + w * 16 + (l >> 2);
#pragma unroll
    for (int jt = 0; jt < 16; jt++) {
        const int col = h * H_DIM + jt * 8 + (l & 3) * 2;
        *reinterpret_cast<__half2*>(&Og[rA * D_MODEL + col]) =
            __floats2half2_rn(o[jt][0] * invA, o[jt][1] * invA);
        *reinterpret_cast<__half2*>(&Og[(rA + 8) * D_MODEL + col]) =
            __floats2half2_rn(o[jt][2] * invB, o[jt][3] * invB);
    }
}

// ---------------------------------------------------------------------------
extern "C" void kernel_launch(void* const* d_in, const int* in_sizes, int n_in,
                              void* d_out, int out_size)
{
    const float* x    = (const float*)d_in[0];
    const float* wq_w = (const float*)d_in[1];
    const float* wq_b = (const float*)d_in[2];
    const float* wk_w = (const float*)d_in[3];
    const float* wk_b = (const float*)d_in[4];
    const float* wv_w = (const float*)d_in[5];
    const float* wv_b = (const float*)d_in[6];
    const float* wo_w = (const float*)d_in[7];
    const float* wo_b = (const float*)d_in[8];
    float* out = (float*)d_out;

    __half *xh, *wqh, *wkh, *wvh, *woh, *qh, *kh, *vh, *ah;
    cudaGetSymbolAddress((void**)&xh,  g_xh);
    cudaGetSymbolAddress((void**)&wqh, g_wqh);
    cudaGetSymbolAddress((void**)&wkh, g_wkh);
    cudaGetSymbolAddress((void**)&wvh, g_wvh);
    cudaGetSymbolAddress((void**)&woh, g_woh);
    cudaGetSymbolAddress((void**)&qh,  g_qh);
    cudaGetSymbolAddress((void**)&kh,  g_kh);
    cudaGetSymbolAddress((void**)&vh,  g_vh);
    cudaGetSymbolAddress((void**)&ah,  g_ah);

    cudaFuncSetAttribute(gemm_h_kernel<__half>,
                         cudaFuncAttributeMaxDynamicSharedMemorySize, GEMM_SMEM);
    cudaFuncSetAttribute(gemm_h_kernel<float>,
                         cudaFuncAttributeMaxDynamicSharedMemorySize, GEMM_SMEM);
    cudaFuncSetAttribute(attn_h_kernel,
                         cudaFuncAttributeMaxDynamicSharedMemorySize, ATTN_SMEM);

    // fp32 -> fp16 conversions
    const int NB = 1024;   // threads per block for cvt (256) * 4 elems
    cvt_kernel<<<(N_TOK * D_MODEL) / NB, 256>>>(x, xh, N_TOK * D_MODEL);
    cvt_kernel<<<(D_MODEL * D_MODEL) / NB, 256>>>(wq_w, wqh, D_MODEL * D_MODEL);
    cvt_kernel<<<(H_DIM * D_MODEL) / NB, 256>>>(wk_w, wkh, H_DIM * D_MODEL);
    cvt_kernel<<<(H_DIM * D_MODEL) / NB, 256>>>(wv_w, wvh, H_DIM * D_MODEL);
    cvt_kernel<<<(D_MODEL * D_MODEL) / NB, 256>>>(wo_w, woh, D_MODEL * D_MODEL);

    // QKV projections (fp16 HMMA)
    gemm_h_kernel<__half><<<dim3(D_MODEL / 128, N_TOK / 128), 256, GEMM_SMEM>>>(
        xh, wqh, wq_b, qh, N_TOK, D_MODEL, D_MODEL);
    gemm_h_kernel<__half><<<dim3(1, N_TOK / 128), 256, GEMM_SMEM>>>(
        xh, wkh, wk_b, kh, N_TOK, H_DIM, D_MODEL);
    gemm_h_kernel<__half><<<dim3(1, N_TOK / 128), 256, GEMM_SMEM>>>(
        xh, wvh, wv_b, vh, N_TOK, H_DIM, D_MODEL);

    // Causal flash attention (fp16 HMMA)
    attn_h_kernel<<<dim3(T_SEQ / 128, N_HEAD, 2), 256, ATTN_SMEM>>>(qh, kh, vh, ah);

    // Output projection (fp32 out)
    gemm_h_kernel<float><<<dim3(D_MODEL / 128, N_TOK / 128), 256, GEMM_SMEM>>>(
        ah, woh, wo_b, out, N_TOK, D_MODEL, D_MODEL);
}

// round 6
// speedup vs baseline: 9.8530x; 1.1322x over previous
#include <cuda_runtime.h>
#include <cuda_fp16.h>
#include <math.h>
#include <stdint.h>

#define D_MODEL 4096
#define N_TOK   4096   // B*T
#define T_SEQ   2048
#define N_HEAD  32
#define H_DIM   128

// ---------------------------------------------------------------------------
// Scratch (allocation-free rule: __device__ globals)
// ---------------------------------------------------------------------------
__device__ __half g_xh [(size_t)N_TOK * D_MODEL];
__device__ __half g_wqh[(size_t)D_MODEL * D_MODEL];
__device__ __half g_wkh[(size_t)H_DIM * D_MODEL];
__device__ __half g_wvh[(size_t)H_DIM * D_MODEL];
__device__ __half g_woh[(size_t)D_MODEL * D_MODEL];
__device__ __half g_qh [(size_t)N_TOK * D_MODEL];
__device__ __half g_kh [(size_t)N_TOK * H_DIM];
__device__ __half g_vh [(size_t)N_TOK * H_DIM];
__device__ __half g_ah [(size_t)N_TOK * D_MODEL];
__device__ float  g_kvpart[(size_t)2 * 8 * N_TOK * H_DIM];   // [kv][split][row][col]

// ---------------------------------------------------------------------------
// PTX helpers (base sm_103 feature set: cp.async / ldmatrix / mma.sync)
// ---------------------------------------------------------------------------
__device__ __forceinline__ uint32_t smem_u32(const void* p) {
    uint32_t a;
    asm("{ .reg .u64 t; cvta.to.shared.u64 t, %1; cvt.u32.u64 %0, t; }"
        : "=r"(a) : "l"(p));
    return a;
}

#define CP_ASYNC16(saddr, gptr) \
    asm volatile("cp.async.cg.shared.global [%0], [%1], 16;" \
                 :: "r"(saddr), "l"(gptr))
#define CP_COMMIT()  asm volatile("cp.async.commit_group;" ::: "memory")
#define CP_WAIT(n)   asm volatile("cp.async.wait_group %0;" :: "n"(n) : "memory")

#define LDSM_X4(r0, r1, r2, r3, addr) \
    asm volatile("ldmatrix.sync.aligned.m8n8.x4.shared.b16 {%0,%1,%2,%3}, [%4];" \
                 : "=r"(r0), "=r"(r1), "=r"(r2), "=r"(r3) : "r"(addr))
#define LDSM_X4_T(r0, r1, r2, r3, addr) \
    asm volatile("ldmatrix.sync.aligned.m8n8.x4.trans.shared.b16 {%0,%1,%2,%3}, [%4];" \
                 : "=r"(r0), "=r"(r1), "=r"(r2), "=r"(r3) : "r"(addr))

#define MMA16816(d, a0, a1, a2, a3, b0, b1) \
    asm volatile("mma.sync.aligned.m16n8k16.row.col.f32.f16.f16.f32 " \
                 "{%0,%1,%2,%3}, {%4,%5,%6,%7}, {%8,%9}, {%0,%1,%2,%3};" \
                 : "+f"((d)[0]), "+f"((d)[1]), "+f"((d)[2]), "+f"((d)[3]) \
                 : "r"(a0), "r"(a1), "r"(a2), "r"(a3), "r"(b0), "r"(b1))

__device__ __forceinline__ uint32_t h2u(__half2 h) {
    return *reinterpret_cast<uint32_t*>(&h);
}

// ---------------------------------------------------------------------------
// fp32 -> fp16 convert (vectorized)
// ---------------------------------------------------------------------------
__global__ void cvt_kernel(const float* __restrict__ in, __half* __restrict__ out,
                           int n) {
    int i = (blockIdx.x * blockDim.x + threadIdx.x) * 4;
    if (i < n) {
        float4 f = *(const float4*)(in + i);
        __half2 h0 = __floats2half2_rn(f.x, f.y);
        __half2 h1 = __floats2half2_rn(f.z, f.w);
        *(uint2*)(out + i) = make_uint2(h2u(h0), h2u(h1));
    }
}

// ---------------------------------------------------------------------------
// Fused QKV kernel.
//   blockIdx.x in [0,1024):     Q GEMM tile (mt = x>>5, nt = x&31), full K.
//   blockIdx.x in [1024,1536):  K/V split-K partial: kv = t>>8, mt = (t&255)>>3,
//                               split = t&7 -> 8 k-iters, fp32 partial out.
// Both paths: BM=BN=128, BK=64, 256 thr / 8 warps (warp 64x32), 3-stage
// cp.async, XOR-swizzled smem, ldmatrix + mma.sync m16n8k16.
// ---------------------------------------------------------------------------
#define GSTAGES 3
#define GEMM_SMEM (GSTAGES * 32768)

__global__ __launch_bounds__(256) void qkv_kernel(
    const __half* __restrict__ Xh,
    const __half* __restrict__ Wq, const __half* __restrict__ Wk,
    const __half* __restrict__ Wv,
    const float* __restrict__ qbias,
    __half* __restrict__ Qout, float* __restrict__ part)
{
    extern __shared__ char smc[];
    const uint32_t sb = smem_u32(smc);
    const int tid = threadIdx.x;
    const int l = tid & 31, w = tid >> 5;
    const int wm = (w >> 2) * 64, wn = (w & 3) * 32;

    const int bx = blockIdx.x;
    const bool isQ = bx < 1024;
    int m0, n0, kt0, NT, kv = 0, sp = 0;
    const __half* Wg_base;
    if (isQ) {
        m0 = (bx >> 5) * 128; n0 = (bx & 31) * 128; kt0 = 0; NT = 64;
        Wg_base = Wq;
    } else {
        const int t2 = bx - 1024;
        kv = t2 >> 8;
        const int rem = t2 & 255;
        m0 = (rem >> 3) * 128; n0 = 0; sp = rem & 7; kt0 = sp * 8; NT = 8;
        Wg_base = kv ? Wv : Wk;
    }

    const int sr = tid >> 3;   // 0..31
    const int sc = tid & 7;    // chunk 0..7
    const __half* Ag = Xh + (size_t)(m0 + sr) * D_MODEL + sc * 8;
    const __half* Wg = Wg_base + (size_t)(n0 + sr) * D_MODEL + sc * 8;

    auto stage = [&](int kt) {
        const int st = kt % GSTAGES;
        const uint32_t ab = sb + st * 32768;
        const uint32_t bb = ab + 16384;
        const int k0 = (kt0 + kt) * 64;
#pragma unroll
        for (int it = 0; it < 4; it++) {
            const int r = sr + it * 32;
            const uint32_t soff = (uint32_t)(r * 128 + ((sc ^ (r & 7)) * 16));
            CP_ASYNC16(ab + soff, Ag + (size_t)(it * 32) * D_MODEL + k0);
            CP_ASYNC16(bb + soff, Wg + (size_t)(it * 32) * D_MODEL + k0);
        }
    };

    float acc[4][4][4];
#pragma unroll
    for (int i = 0; i < 4; i++)
#pragma unroll
        for (int j = 0; j < 4; j++)
#pragma unroll
            for (int c = 0; c < 4; c++) acc[i][j][c] = 0.0f;

    stage(0); CP_COMMIT();
    stage(1); CP_COMMIT();

#pragma unroll 1
    for (int kt = 0; kt < NT; kt++) {
        if (kt + 2 < NT) { stage(kt + 2); CP_COMMIT(); CP_WAIT(2); }
        else if (kt + 1 < NT) { CP_WAIT(1); }
        else { CP_WAIT(0); }
        __syncthreads();

        const int st = kt % GSTAGES;
        const uint32_t ab = sb + st * 32768;
        const uint32_t bb = ab + 16384;

#pragma unroll
        for (int ks = 0; ks < 4; ks++) {
            uint32_t a[4][4], b[4][2];
#pragma unroll
            for (int i = 0; i < 4; i++) {
                const int row = wm + i * 16 + (l & 15);
                const int ch = ks * 2 + (l >> 4);
                LDSM_X4(a[i][0], a[i][1], a[i][2], a[i][3],
                        ab + row * 128 + ((ch ^ (row & 7)) * 16));
            }
#pragma unroll
            for (int jj = 0; jj < 2; jj++) {
                const int nrow = wn + jj * 16 + (l & 7) + ((l >> 4) & 1) * 8;
                const int ch = ks * 2 + ((l >> 3) & 1);
                LDSM_X4(b[jj * 2][0], b[jj * 2][1], b[jj * 2 + 1][0], b[jj * 2 + 1][1],
                        bb + nrow * 128 + ((ch ^ (nrow & 7)) * 16));
            }
#pragma unroll
            for (int i = 0; i < 4; i++)
#pragma unroll
                for (int j = 0; j < 4; j++)
                    MMA16816(acc[i][j], a[i][0], a[i][1], a[i][2], a[i][3],
                             b[j][0], b[j][1]);
        }
        __syncthreads();
    }

    if (isQ) {
#pragma unroll
        for (int i = 0; i < 4; i++) {
#pragma unroll
            for (int j = 0; j < 4; j++) {
                const int row = m0 + wm + i * 16 + (l >> 2);
                const int col = n0 + wn + j * 8 + (l & 3) * 2;
                const float b0 = qbias[col], b1 = qbias[col + 1];
                *reinterpret_cast<__half2*>(&Qout[(size_t)row * D_MODEL + col]) =
                    __floats2half2_rn(acc[i][j][0] + b0, acc[i][j][1] + b1);
                *reinterpret_cast<__half2*>(&Qout[(size_t)(row + 8) * D_MODEL + col]) =
                    __floats2half2_rn(acc[i][j][2] + b0, acc[i][j][3] + b1);
            }
        }
    } else {
        float* P = part + ((size_t)(kv * 8 + sp) * N_TOK + m0) * H_DIM;
#pragma unroll
        for (int i = 0; i < 4; i++) {
#pragma unroll
            for (int j = 0; j < 4; j++) {
                const int row = wm + i * 16 + (l >> 2);
                const int col = wn + j * 8 + (l & 3) * 2;
                *reinterpret_cast<float2*>(&P[(size_t)row * H_DIM + col]) =
                    make_float2(acc[i][j][0], acc[i][j][1]);
                *reinterpret_cast<float2*>(&P[(size_t)(row + 8) * H_DIM + col]) =
                    make_float2(acc[i][j][2], acc[i][j][3]);
            }
        }
    }
}

// ---------------------------------------------------------------------------
// K/V split-K reduce: sum 8 partials + bias -> fp16
// ---------------------------------------------------------------------------
__global__ void kv_reduce_kernel(const float* __restrict__ part,
                                 const float* __restrict__ kbias,
                                 const float* __restrict__ vbias,
                                 __half* __restrict__ Kh, __half* __restrict__ Vh)
{
    const int i = (blockIdx.x * blockDim.x + threadIdx.x) * 4;   // over 2*4096*128
    const int half_n = N_TOK * H_DIM;
    const int kv = i >= half_n;
    const int j = i - kv * half_n;
    const int col = j & (H_DIM - 1);

    float4 s = make_float4(0.f, 0.f, 0.f, 0.f);
#pragma unroll
    for (int sp = 0; sp < 8; sp++) {
        float4 p = *(const float4*)&part[((size_t)(kv * 8 + sp) * N_TOK * H_DIM) + j];
        s.x += p.x; s.y += p.y; s.z += p.z; s.w += p.w;
    }
    const float* bias = kv ? vbias : kbias;
    float4 b = *(const float4*)&bias[col];
    __half* out = kv ? Vh : Kh;
    __half2 h0 = __floats2half2_rn(s.x + b.x, s.y + b.y);
    __half2 h1 = __floats2half2_rn(s.z + b.z, s.w + b.w);
    *(uint2*)(out + j) = make_uint2(h2u(h0), h2u(h1));
}

// ---------------------------------------------------------------------------
// Flash attention (causal), fp16 mma. CTA = 128 queries x head x batch.
// LPT scheduling: qb = 15 - blockIdx.x (longest CTAs first).
// ---------------------------------------------------------------------------
#define ATTN_SMEM (32768 + 2 * 32768)

__global__ __launch_bounds__(256) void attn_h_kernel(
    const __half* __restrict__ Qg, const __half* __restrict__ Kg,
    const __half* __restrict__ Vg, __half* __restrict__ Og)
{
    extern __shared__ char smc[];
    const uint32_t sb = smem_u32(smc);
    const int tid = threadIdx.x;
    const int l = tid & 31, w = tid >> 5;
    const int qb = (T_SEQ / 128 - 1) - blockIdx.x;   // LPT: long CTAs first
    const int h = blockIdx.y, b = blockIdx.z;
    const size_t tok0 = (size_t)b * T_SEQ;
    const float fscale = 0.08838834764831845f;   // 1/sqrt(128)

    {
#pragma unroll
        for (int it = 0; it < 8; it++) {
            const int idx = tid + it * 256;
            const int r = idx >> 4, ch = idx & 15;
            const __half* g = Qg + (tok0 + qb * 128 + r) * D_MODEL + h * H_DIM + ch * 8;
            CP_ASYNC16(sb + r * 256 + ((ch ^ (r & 7)) * 16), g);
        }
    }

    auto stage_kv = [&](int kb) {
        const uint32_t kbb = sb + 32768 + (kb & 1) * 32768;
        const uint32_t vbb = kbb + 16384;
#pragma unroll
        for (int it = 0; it < 4; it++) {
            const int idx = tid + it * 256;
            const int r = idx >> 4, ch = idx & 15;
            const uint32_t off = (uint32_t)(r * 256 + ((ch ^ (r & 7)) * 16));
            CP_ASYNC16(kbb + off, Kg + (tok0 + kb * 64 + r) * H_DIM + ch * 8);
            CP_ASYNC16(vbb + off, Vg + (tok0 + kb * 64 + r) * H_DIM + ch * 8);
        }
    };

    stage_kv(0); CP_COMMIT();

    float o[16][4];
#pragma unroll
    for (int jt = 0; jt < 16; jt++)
#pragma unroll
        for (int c = 0; c < 4; c++) o[jt][c] = 0.0f;
    float mA = -1e30f, mB = -1e30f, lA = 0.0f, lB = 0.0f;

    const int nb = 2 * qb + 2;
    const int rowA = qb * 128 + w * 16 + (l >> 2);
    const int wmax = qb * 128 + w * 16 + 15;

#pragma unroll 1
    for (int kb = 0; kb < nb; kb++) {
        if (kb + 1 < nb) { stage_kv(kb + 1); CP_COMMIT(); CP_WAIT(1); }
        else { CP_WAIT(0); }
        __syncthreads();

        if (kb * 64 <= wmax) {
            const uint32_t kbb = sb + 32768 + (kb & 1) * 32768;
            const uint32_t vbb = kbb + 16384;

            float s[8][4];
#pragma unroll
            for (int j = 0; j < 8; j++)
#pragma unroll
                for (int c = 0; c < 4; c++) s[j][c] = 0.0f;

#pragma unroll
            for (int ks = 0; ks < 8; ks++) {
                uint32_t a0, a1, a2, a3;
                {
                    const int row = w * 16 + (l & 15);
                    const int ch = ks * 2 + (l >> 4);
                    LDSM_X4(a0, a1, a2, a3, sb + row * 256 + ((ch ^ (row & 7)) * 16));
                }
                uint32_t bf[8][2];
#pragma unroll
                for (int jj = 0; jj < 4; jj++) {
                    const int nrow = jj * 16 + (l & 7) + ((l >> 4) & 1) * 8;
                    const int ch = ks * 2 + ((l >> 3) & 1);
                    LDSM_X4(bf[jj * 2][0], bf[jj * 2][1],
                            bf[jj * 2 + 1][0], bf[jj * 2 + 1][1],
                            kbb + nrow * 256 + ((ch ^ (nrow & 7)) * 16));
                }
#pragma unroll
                for (int j = 0; j < 8; j++)
                    MMA16816(s[j], a0, a1, a2, a3, bf[j][0], bf[j][1]);
            }

            if (kb >= 2 * qb) {
#pragma unroll
                for (int j = 0; j < 8; j++) {
                    const int col = kb * 64 + j * 8 + (l & 3) * 2;
                    if (col > rowA)     s[j][0] = -1e30f;
                    if (col + 1 > rowA) s[j][1] = -1e30f;
                    if (col > rowA + 8)     s[j][2] = -1e30f;
                    if (col + 1 > rowA + 8) s[j][3] = -1e30f;
                }
            }

            float mlA = -1e30f, mlB = -1e30f;
#pragma unroll
            for (int j = 0; j < 8; j++) {
                mlA = fmaxf(mlA, fmaxf(s[j][0], s[j][1]));
                mlB = fmaxf(mlB, fmaxf(s[j][2], s[j][3]));
            }
            mlA = fmaxf(mlA, __shfl_xor_sync(0xffffffffu, mlA, 1));
            mlA = fmaxf(mlA, __shfl_xor_sync(0xffffffffu, mlA, 2));
            mlB = fmaxf(mlB, __shfl_xor_sync(0xffffffffu, mlB, 1));
            mlB = fmaxf(mlB, __shfl_xor_sync(0xffffffffu, mlB, 2));

            const float mnA = fmaxf(mA, mlA), mnB = fmaxf(mB, mlB);
            const float aA = __expf((mA - mnA) * fscale);
            const float aB = __expf((mB - mnB) * fscale);
            mA = mnA; mB = mnB;

            uint32_t pA[8], pB[8];
            float sumA = 0.0f, sumB = 0.0f;
#pragma unroll
            for (int j = 0; j < 8; j++) {
                const float e0 = __expf((s[j][0] - mA) * fscale);
                const float e1 = __expf((s[j][1] - mA) * fscale);
                const float e2 = __expf((s[j][2] - mB) * fscale);
                const float e3 = __expf((s[j][3] - mB) * fscale);
                sumA += e0 + e1; sumB += e2 + e3;
                pA[j] = h2u(__floats2half2_rn(e0, e1));
                pB[j] = h2u(__floats2half2_rn(e2, e3));
            }
            sumA += __shfl_xor_sync(0xffffffffu, sumA, 1);
            sumA += __shfl_xor_sync(0xffffffffu, sumA, 2);
            sumB += __shfl_xor_sync(0xffffffffu, sumB, 1);
            sumB += __shfl_xor_sync(0xffffffffu, sumB, 2);
            lA = lA * aA + sumA;
            lB = lB * aB + sumB;

#pragma unroll
            for (int jt = 0; jt < 16; jt++) {
                o[jt][0] *= aA; o[jt][1] *= aA;
                o[jt][2] *= aB; o[jt][3] *= aB;
            }

#pragma unroll
            for (int ks2 = 0; ks2 < 4; ks2++) {
                const uint32_t pa0 = pA[2 * ks2],     pa1 = pB[2 * ks2];
                const uint32_t pa2 = pA[2 * ks2 + 1], pa3 = pB[2 * ks2 + 1];
                const int key = ks2 * 16 + (l & 7) + ((l >> 3) & 1) * 8;
#pragma unroll
                for (int u = 0; u < 8; u++) {
                    const int ch = 2 * u + (l >> 4);
                    uint32_t v0, v1, v2, v3;
                    LDSM_X4_T(v0, v1, v2, v3,
                              vbb + key * 256 + ((ch ^ (key & 7)) * 16));
                    MMA16816(o[2 * u],     pa0, pa1, pa2, pa3, v0, v1);
                    MMA16816(o[2 * u + 1], pa0, pa1, pa2, pa3, v2, v3);
                }
            }
        }
        __syncthreads();
    }

    const float invA = 1.0f / lA, invB = 1.0f / lB;
    const size_t rA = tok0 + qb * 128 + w * 16 + (l >> 2);
#pragma unroll
    for (int jt = 0; jt < 16; jt++) {
        const int col = h * H_DIM + jt * 8 + (l & 3) * 2;
        *reinterpret_cast<__half2*>(&Og[rA * D_MODEL + col]) =
            __floats2half2_rn(o[jt][0] * invA, o[jt][1] * invA);
        *reinterpret_cast<__half2*>(&Og[(rA + 8) * D_MODEL + col]) =
            __floats2half2_rn(o[jt][2] * invB, o[jt][3] * invB);
    }
}

// ---------------------------------------------------------------------------
// O-projection GEMM (fp32 out), same structure as qkv Q-path.
// ---------------------------------------------------------------------------
__global__ __launch_bounds__(256) void oproj_kernel(
    const __half* __restrict__ A, const __half* __restrict__ W,
    const float* __restrict__ bias, float* __restrict__ C)
{
    extern __shared__ char smc[];
    const uint32_t sb = smem_u32(smc);
    const int tid = threadIdx.x;
    const int l = tid & 31, w = tid >> 5;
    const int m0 = blockIdx.y * 128, n0 = blockIdx.x * 128;
    const int wm = (w >> 2) * 64, wn = (w & 3) * 32;

    const int sr = tid >> 3;
    const int sc = tid & 7;
    const __half* Ag = A + (size_t)(m0 + sr) * D_MODEL + sc * 8;
    const __half* Wg = W + (size_t)(n0 + sr) * D_MODEL + sc * 8;

    auto stage = [&](int kt) {
        const int st = kt % GSTAGES;
        const uint32_t ab = sb + st * 32768;
        const uint32_t bb = ab + 16384;
        const int k0 = kt * 64;
#pragma unroll
        for (int it = 0; it < 4; it++) {
            const int r = sr + it * 32;
            const uint32_t soff = (uint32_t)(r * 128 + ((sc ^ (r & 7)) * 16));
            CP_ASYNC16(ab + soff, Ag + (size_t)(it * 32) * D_MODEL + k0);
            CP_ASYNC16(bb + soff, Wg + (size_t)(it * 32) * D_MODEL + k0);
        }
    };

    float acc[4][4][4];
#pragma unroll
    for (int i = 0; i < 4; i++)
#pragma unroll
        for (int j = 0; j < 4; j++)
#pragma unroll
            for (int c = 0; c < 4; c++) acc[i][j][c] = 0.0f;

    stage(0); CP_COMMIT();
    stage(1); CP_COMMIT();

    const int NT = D_MODEL / 64;
#pragma unroll 1
    for (int kt = 0; kt < NT; kt++) {
        if (kt + 2 < NT) { stage(kt + 2); CP_COMMIT(); CP_WAIT(2); }
        else if (kt + 1 < NT) { CP_WAIT(1); }
        else { CP_WAIT(0); }
        __syncthreads();

        const int st = kt % GSTAGES;
        const uint32_t ab = sb + st * 32768;
        const uint32_t bb = ab + 16384;

#pragma unroll
        for (int ks = 0; ks < 4; ks++) {
            uint32_t a[4][4], b[4][2];
#pragma unroll
            for (int i = 0; i < 4; i++) {
                const int row = wm + i * 16 + (l & 15);
                const int ch = ks * 2 + (l >> 4);
                LDSM_X4(a[i][0], a[i][1], a[i][2], a[i][3],
                        ab + row * 128 + ((ch ^ (row & 7)) * 16));
            }
#pragma unroll
            for (int jj = 0; jj < 2; jj++) {
                const int nrow = wn + jj * 16 + (l & 7) + ((l >> 4) & 1) * 8;
                const int ch = ks * 2 + ((l >> 3) & 1);
                LDSM_X4(b[jj * 2][0], b[jj * 2][1], b[jj * 2 + 1][0], b[jj * 2 + 1][1],
                        bb + nrow * 128 + ((ch ^ (nrow & 7)) * 16));
            }
#pragma unroll
            for (int i = 0; i < 4; i++)
#pragma unroll
                for (int j = 0; j < 4; j++)
                    MMA16816(acc[i][j], a[i][0], a[i][1], a[i][2], a[i][3],
                             b[j][0], b[j][1]);
        }
        __syncthreads();
    }

#pragma unroll
    for (int i = 0; i < 4; i++) {
#pragma unroll
        for (int j = 0; j < 4; j++) {
            const int row = m0 + wm + i * 16 + (l >> 2);
            const int col = n0 + wn + j * 8 + (l & 3) * 2;
            const float b0 = bias[col], b1 = bias[col + 1];
            *reinterpret_cast<float2*>(&C[(size_t)row * D_MODEL + col]) =
                make_float2(acc[i][j][0] + b0, acc[i][j][1] + b1);
            *reinterpret_cast<float2*>(&C[(size_t)(row + 8) * D_MODEL + col]) =
                make_float2(acc[i][j][2] + b0, acc[i][j][3] + b1);
        }
    }
}

// ---------------------------------------------------------------------------
extern "C" void kernel_launch(void* const* d_in, const int* in_sizes, int n_in,
                              void* d_out, int out_size)
{
    const float* x    = (const float*)d_in[0];
    const float* wq_w = (const float*)d_in[1];
    const float* wq_b = (const float*)d_in[2];
    const float* wk_w = (const float*)d_in[3];
    const float* wk_b = (const float*)d_in[4];
    const float* wv_w = (const float*)d_in[5];
    const float* wv_b = (const float*)d_in[6];
    const float* wo_w = (const float*)d_in[7];
    const float* wo_b = (const float*)d_in[8];
    float* out = (float*)d_out;

    __half *xh, *wqh, *wkh, *wvh, *woh, *qh, *kh, *vh, *ah;
    float* part;
    cudaGetSymbolAddress((void**)&xh,  g_xh);
    cudaGetSymbolAddress((void**)&wqh, g_wqh);
    cudaGetSymbolAddress((void**)&wkh, g_wkh);
    cudaGetSymbolAddress((void**)&wvh, g_wvh);
    cudaGetSymbolAddress((void**)&woh, g_woh);
    cudaGetSymbolAddress((void**)&qh,  g_qh);
    cudaGetSymbolAddress((void**)&kh,  g_kh);
    cudaGetSymbolAddress((void**)&vh,  g_vh);
    cudaGetSymbolAddress((void**)&ah,  g_ah);
    cudaGetSymbolAddress((void**)&part, g_kvpart);

    cudaFuncSetAttribute(qkv_kernel,
                         cudaFuncAttributeMaxDynamicSharedMemorySize, GEMM_SMEM);
    cudaFuncSetAttribute(oproj_kernel,
                         cudaFuncAttributeMaxDynamicSharedMemorySize, GEMM_SMEM);
    cudaFuncSetAttribute(attn_h_kernel,
                         cudaFuncAttributeMaxDynamicSharedMemorySize, ATTN_SMEM);

    // fp32 -> fp16 conversions
    const int NB = 1024;
    cvt_kernel<<<(N_TOK * D_MODEL) / NB, 256>>>(x, xh, N_TOK * D_MODEL);
    cvt_kernel<<<(D_MODEL * D_MODEL) / NB, 256>>>(wq_w, wqh, D_MODEL * D_MODEL);
    cvt_kernel<<<(H_DIM * D_MODEL) / NB, 256>>>(wk_w, wkh, H_DIM * D_MODEL);
    cvt_kernel<<<(H_DIM * D_MODEL) / NB, 256>>>(wv_w, wvh, H_DIM * D_MODEL);
    cvt_kernel<<<(D_MODEL * D_MODEL) / NB, 256>>>(wo_w, woh, D_MODEL * D_MODEL);

    // Fused Q + split-K K/V projections
    qkv_kernel<<<1536, 256, GEMM_SMEM>>>(xh, wqh, wkh, wvh, wq_b, qh, part);
    kv_reduce_kernel<<<(2 * N_TOK * H_DIM) / NB, 256>>>(part, wk_b, wv_b, kh, vh);

    // Causal flash attention (LPT order)
    attn_h_kernel<<<dim3(T_SEQ / 128, N_HEAD, 2), 256, ATTN_SMEM>>>(qh, kh, vh, ah);

    // Output projection (fp32 out)
    oproj_kernel<<<dim3(D_MODEL / 128, N_TOK / 128), 256, GEMM_SMEM>>>(
        ah, woh, wo_b, out);
}

// round 8
// speedup vs baseline: 10.1752x; 1.0327x over previous
#include <cuda_runtime.h>
#include <cuda_fp16.h>
#include <math.h>
#include <stdint.h>

#define D_MODEL 4096
#define N_TOK   4096   // B*T
#define T_SEQ   2048
#define N_HEAD  32
#define H_DIM   128

// ---------------------------------------------------------------------------
// Scratch (allocation-free rule: __device__ globals)
// ---------------------------------------------------------------------------
__device__ __half g_xh [(size_t)N_TOK * D_MODEL];
__device__ __half g_wqh[(size_t)D_MODEL * D_MODEL];
__device__ __half g_wkh[(size_t)H_DIM * D_MODEL];
__device__ __half g_wvh[(size_t)H_DIM * D_MODEL];
__device__ __half g_woh[(size_t)D_MODEL * D_MODEL];
__device__ __half g_qh [(size_t)N_TOK * D_MODEL];
__device__ __half g_kh [(size_t)N_TOK * H_DIM];
__device__ __half g_vh [(size_t)N_TOK * H_DIM];
__device__ __half g_ah [(size_t)N_TOK * D_MODEL];
__device__ float  g_kvpart[(size_t)2 * 8 * N_TOK * H_DIM];   // [kv][split][row][col]

// ---------------------------------------------------------------------------
// PTX helpers (base sm_103 feature set: cp.async / ldmatrix / mma.sync)
// ---------------------------------------------------------------------------
__device__ __forceinline__ uint32_t smem_u32(const void* p) {
    uint32_t a;
    asm("{ .reg .u64 t; cvta.to.shared.u64 t, %1; cvt.u32.u64 %0, t; }"
        : "=r"(a) : "l"(p));
    return a;
}

#define CP_ASYNC16(saddr, gptr) \
    asm volatile("cp.async.cg.shared.global [%0], [%1], 16;" \
                 :: "r"(saddr), "l"(gptr))
#define CP_COMMIT()  asm volatile("cp.async.commit_group;" ::: "memory")
#define CP_WAIT(n)   asm volatile("cp.async.wait_group %0;" :: "n"(n) : "memory")

#define LDSM_X4(r0, r1, r2, r3, addr) \
    asm volatile("ldmatrix.sync.aligned.m8n8.x4.shared.b16 {%0,%1,%2,%3}, [%4];" \
                 : "=r"(r0), "=r"(r1), "=r"(r2), "=r"(r3) : "r"(addr))
#define LDSM_X4_T(r0, r1, r2, r3, addr) \
    asm volatile("ldmatrix.sync.aligned.m8n8.x4.trans.shared.b16 {%0,%1,%2,%3}, [%4];" \
                 : "=r"(r0), "=r"(r1), "=r"(r2), "=r"(r3) : "r"(addr))

#define MMA16816(d, a0, a1, a2, a3, b0, b1) \
    asm volatile("mma.sync.aligned.m16n8k16.row.col.f32.f16.f16.f32 " \
                 "{%0,%1,%2,%3}, {%4,%5,%6,%7}, {%8,%9}, {%0,%1,%2,%3};" \
                 : "+f"((d)[0]), "+f"((d)[1]), "+f"((d)[2]), "+f"((d)[3]) \
                 : "r"(a0), "r"(a1), "r"(a2), "r"(a3), "r"(b0), "r"(b1))

__device__ __forceinline__ uint32_t h2u(__half2 h) {
    return *reinterpret_cast<uint32_t*>(&h);
}

// ---------------------------------------------------------------------------
// Merged fp32 -> fp16 convert: one launch for x, wq, wk, wv, wo.
// ---------------------------------------------------------------------------
#define NX  ((size_t)N_TOK * D_MODEL)     // 16777216
#define NW  ((size_t)D_MODEL * D_MODEL)   // 16777216
#define NKV ((size_t)H_DIM * D_MODEL)     // 524288
#define CVT_TOTAL (3 * NX + 2 * NKV)      // x==wq==wo size

__global__ void cvt_all_kernel(
    const float* __restrict__ x,  const float* __restrict__ wq,
    const float* __restrict__ wk, const float* __restrict__ wv,
    const float* __restrict__ wo,
    __half* __restrict__ xh, __half* __restrict__ wqh,
    __half* __restrict__ wkh, __half* __restrict__ wvh,
    __half* __restrict__ woh)
{
    size_t i = ((size_t)blockIdx.x * blockDim.x + threadIdx.x) * 4;
    const float* src; __half* dst; size_t off;
    if (i < NX)                     { src = x;  dst = xh;  off = i; }
    else if (i < NX + NW)           { src = wq; dst = wqh; off = i - NX; }
    else if (i < NX + NW + NKV)     { src = wk; dst = wkh; off = i - NX - NW; }
    else if (i < NX + NW + 2 * NKV) { src = wv; dst = wvh; off = i - NX - NW - NKV; }
    else                            { src = wo; dst = woh; off = i - NX - NW - 2 * NKV; }
    float4 f = *(const float4*)(src + off);
    __half2 h0 = __floats2half2_rn(f.x, f.y);
    __half2 h1 = __floats2half2_rn(f.z, f.w);
    *(uint2*)(dst + off) = make_uint2(h2u(h0), h2u(h1));
}

// ---------------------------------------------------------------------------
// GEMM core: BM=BN=128, BK=64, 128 threads / 4 warps, warp tile 64x64.
// 3-stage cp.async, XOR-swizzled smem, ldmatrix + mma.sync m16n8k16.
// MMA/LDSM ratio 4.0 (vs 2.67 at 64x32); 2 CTAs/SM.
// ---------------------------------------------------------------------------
#define GSTAGES 3
#define GEMM_SMEM (GSTAGES * 32768)

// kv<0: Q path (fp16 out + bias).  kv>=0: split-K partial (fp32, no bias).
struct GemmOut {
    __half* qout; float* part; const float* bias;
    int n_stride; int m0; int n0;
};

__device__ __forceinline__ void gemm_core(
    const __half* __restrict__ Ag0, const __half* __restrict__ Wg0,
    uint32_t sb, int NT, int kt0, int tid, float acc[4][8][4])
{
    const int sr = tid >> 3;   // 0..15
    const int sc = tid & 7;    // chunk 0..7
    const int l = tid & 31, w = tid >> 5;
    const int wm = (w & 1) * 64, wn = (w >> 1) * 64;

    const __half* Ag = Ag0 + (size_t)sr * D_MODEL + sc * 8;
    const __half* Wg = Wg0 + (size_t)sr * D_MODEL + sc * 8;

    auto stage = [&](int kt) {
        const int st = kt % GSTAGES;
        const uint32_t ab = sb + st * 32768;
        const uint32_t bb = ab + 16384;
        const int k0 = (kt0 + kt) * 64;
#pragma unroll
        for (int it = 0; it < 8; it++) {
            const int r = sr + it * 16;
            const uint32_t soff = (uint32_t)(r * 128 + ((sc ^ (r & 7)) * 16));
            CP_ASYNC16(ab + soff, Ag + (size_t)(it * 16) * D_MODEL + k0);
            CP_ASYNC16(bb + soff, Wg + (size_t)(it * 16) * D_MODEL + k0);
        }
    };

    stage(0); CP_COMMIT();
    stage(1); CP_COMMIT();

#pragma unroll 1
    for (int kt = 0; kt < NT; kt++) {
        if (kt + 2 < NT) { stage(kt + 2); CP_COMMIT(); CP_WAIT(2); }
        else if (kt + 1 < NT) { CP_WAIT(1); }
        else { CP_WAIT(0); }
        __syncthreads();

        const int st = kt % GSTAGES;
        const uint32_t ab = sb + st * 32768;
        const uint32_t bb = ab + 16384;

#pragma unroll
        for (int ks = 0; ks < 4; ks++) {
            uint32_t a[4][4], b[8][2];
#pragma unroll
            for (int i = 0; i < 4; i++) {
                const int row = wm + i * 16 + (l & 15);
                const int ch = ks * 2 + (l >> 4);
                LDSM_X4(a[i][0], a[i][1], a[i][2], a[i][3],
                        ab + row * 128 + ((ch ^ (row & 7)) * 16));
            }
#pragma unroll
            for (int jj = 0; jj < 4; jj++) {
                const int nrow = wn + jj * 16 + (l & 7) + ((l >> 4) & 1) * 8;
                const int ch = ks * 2 + ((l >> 3) & 1);
                LDSM_X4(b[jj * 2][0], b[jj * 2][1], b[jj * 2 + 1][0], b[jj * 2 + 1][1],
                        bb + nrow * 128 + ((ch ^ (nrow & 7)) * 16));
            }
#pragma unroll
            for (int i = 0; i < 4; i++)
#pragma unroll
                for (int j = 0; j < 8; j++)
                    MMA16816(acc[i][j], a[i][0], a[i][1], a[i][2], a[i][3],
                             b[j][0], b[j][1]);
        }
        __syncthreads();
    }
}

// ---------------------------------------------------------------------------
// Fused QKV kernel (128 threads).
//   blockIdx.x in [0,1024):     Q GEMM tile, full K, fp16 out + bias.
//   blockIdx.x in [1024,1536):  K/V split-K partial (8 k-iters), fp32 out.
// ---------------------------------------------------------------------------
__global__ __launch_bounds__(128) void qkv_kernel(
    const __half* __restrict__ Xh,
    const __half* __restrict__ Wq, const __half* __restrict__ Wk,
    const __half* __restrict__ Wv,
    const float* __restrict__ qbias,
    __half* __restrict__ Qout, float* __restrict__ part)
{
    extern __shared__ char smc[];
    const uint32_t sb = smem_u32(smc);
    const int tid = threadIdx.x;
    const int l = tid & 31, w = tid >> 5;
    const int wm = (w & 1) * 64, wn = (w >> 1) * 64;

    const int bx = blockIdx.x;
    const bool isQ = bx < 1024;
    int m0, n0, kt0, NT, kv = 0, sp = 0;
    const __half* Wg_base;
    if (isQ) {
        m0 = (bx >> 5) * 128; n0 = (bx & 31) * 128; kt0 = 0; NT = 64;
        Wg_base = Wq;
    } else {
        const int t2 = bx - 1024;
        kv = t2 >> 8;
        const int rem = t2 & 255;
        m0 = (rem >> 3) * 128; n0 = 0; sp = rem & 7; kt0 = sp * 8; NT = 8;
        Wg_base = kv ? Wv : Wk;
    }

    float acc[4][8][4];
#pragma unroll
    for (int i = 0; i < 4; i++)
#pragma unroll
        for (int j = 0; j < 8; j++)
#pragma unroll
            for (int c = 0; c < 4; c++) acc[i][j][c] = 0.0f;

    gemm_core(Xh + (size_t)m0 * D_MODEL, Wg_base + (size_t)n0 * D_MODEL,
              sb, NT, kt0, tid, acc);

    if (isQ) {
#pragma unroll
        for (int i = 0; i < 4; i++) {
#pragma unroll
            for (int j = 0; j < 8; j++) {
                const int row = m0 + wm + i * 16 + (l >> 2);
                const int col = n0 + wn + j * 8 + (l & 3) * 2;
                const float b0 = qbias[col], b1 = qbias[col + 1];
                *reinterpret_cast<__half2*>(&Qout[(size_t)row * D_MODEL + col]) =
                    __floats2half2_rn(acc[i][j][0] + b0, acc[i][j][1] + b1);
                *reinterpret_cast<__half2*>(&Qout[(size_t)(row + 8) * D_MODEL + col]) =
                    __floats2half2_rn(acc[i][j][2] + b0, acc[i][j][3] + b1);
            }
        }
    } else {
        float* P = part + ((size_t)(kv * 8 + sp) * N_TOK + m0) * H_DIM;
#pragma unroll
        for (int i = 0; i < 4; i++) {
#pragma unroll
            for (int j = 0; j < 8; j++) {
                const int row = wm + i * 16 + (l >> 2);
                const int col = wn + j * 8 + (l & 3) * 2;
                *reinterpret_cast<float2*>(&P[(size_t)row * H_DIM + col]) =
                    make_float2(acc[i][j][0], acc[i][j][1]);
                *reinterpret_cast<float2*>(&P[(size_t)(row + 8) * H_DIM + col]) =
                    make_float2(acc[i][j][2], acc[i][j][3]);
            }
        }
    }
}

// ---------------------------------------------------------------------------
// O-projection GEMM (fp32 out), 128 threads, same core.
// ---------------------------------------------------------------------------
__global__ __launch_bounds__(128) void oproj_kernel(
    const __half* __restrict__ A, const __half* __restrict__ W,
    const float* __restrict__ bias, float* __restrict__ C)
{
    extern __shared__ char smc[];
    const uint32_t sb = smem_u32(smc);
    const int tid = threadIdx.x;
    const int l = tid & 31, w = tid >> 5;
    const int wm = (w & 1) * 64, wn = (w >> 1) * 64;
    const int m0 = blockIdx.y * 128, n0 = blockIdx.x * 128;

    float acc[4][8][4];
#pragma unroll
    for (int i = 0; i < 4; i++)
#pragma unroll
        for (int j = 0; j < 8; j++)
#pragma unroll
            for (int c = 0; c < 4; c++) acc[i][j][c] = 0.0f;

    gemm_core(A + (size_t)m0 * D_MODEL, W + (size_t)n0 * D_MODEL,
              sb, D_MODEL / 64, 0, tid, acc);

#pragma unroll
    for (int i = 0; i < 4; i++) {
#pragma unroll
        for (int j = 0; j < 8; j++) {
            const int row = m0 + wm + i * 16 + (l >> 2);
            const int col = n0 + wn + j * 8 + (l & 3) * 2;
            const float b0 = bias[col], b1 = bias[col + 1];
            *reinterpret_cast<float2*>(&C[(size_t)row * D_MODEL + col]) =
                make_float2(acc[i][j][0] + b0, acc[i][j][1] + b1);
            *reinterpret_cast<float2*>(&C[(size_t)(row + 8) * D_MODEL + col]) =
                make_float2(acc[i][j][2] + b0, acc[i][j][3] + b1);
        }
    }
}

// ---------------------------------------------------------------------------
// K/V split-K reduce: sum 8 partials + bias -> fp16
// ---------------------------------------------------------------------------
__global__ void kv_reduce_kernel(const float* __restrict__ part,
                                 const float* __restrict__ kbias,
                                 const float* __restrict__ vbias,
                                 __half* __restrict__ Kh, __half* __restrict__ Vh)
{
    const int i = (blockIdx.x * blockDim.x + threadIdx.x) * 4;
    const int half_n = N_TOK * H_DIM;
    const int kv = i >= half_n;
    const int j = i - kv * half_n;
    const int col = j & (H_DIM - 1);

    float4 s = make_float4(0.f, 0.f, 0.f, 0.f);
#pragma unroll
    for (int sp = 0; sp < 8; sp++) {
        float4 p = *(const float4*)&part[((size_t)(kv * 8 + sp) * N_TOK * H_DIM) + j];
        s.x += p.x; s.y += p.y; s.z += p.z; s.w += p.w;
    }
    const float* bias = kv ? vbias : kbias;
    float4 b = *(const float4*)&bias[col];
    __half* out = kv ? Vh : Kh;
    __half2 h0 = __floats2half2_rn(s.x + b.x, s.y + b.y);
    __half2 h1 = __floats2half2_rn(s.z + b.z, s.w + b.w);
    *(uint2*)(out + j) = make_uint2(h2u(h0), h2u(h1));
}

// ---------------------------------------------------------------------------
// Flash attention (causal), fp16 mma. CTA = 128 queries x head x batch.
// LPT scheduling: qb = 15 - blockIdx.x (longest CTAs first).
// ---------------------------------------------------------------------------
#define ATTN_SMEM (32768 + 2 * 32768)

__global__ __launch_bounds__(256) void attn_h_kernel(
    const __half* __restrict__ Qg, const __half* __restrict__ Kg,
    const __half* __restrict__ Vg, __half* __restrict__ Og)
{
    extern __shared__ char smc[];
    const uint32_t sb = smem_u32(smc);
    const int tid = threadIdx.x;
    const int l = tid & 31, w = tid >> 5;
    const int qb = (T_SEQ / 128 - 1) - blockIdx.x;   // LPT: long CTAs first
    const int h = blockIdx.y, b = blockIdx.z;
    const size_t tok0 = (size_t)b * T_SEQ;
    const float fscale = 0.08838834764831845f;   // 1/sqrt(128)

    {
#pragma unroll
        for (int it = 0; it < 8; it++) {
            const int idx = tid + it * 256;
            const int r = idx >> 4, ch = idx & 15;
            const __half* g = Qg + (tok0 + qb * 128 + r) * D_MODEL + h * H_DIM + ch * 8;
            CP_ASYNC16(sb + r * 256 + ((ch ^ (r & 7)) * 16), g);
        }
    }

    auto stage_kv = [&](int kb) {
        const uint32_t kbb = sb + 32768 + (kb & 1) * 32768;
        const uint32_t vbb = kbb + 16384;
#pragma unroll
        for (int it = 0; it < 4; it++) {
            const int idx = tid + it * 256;
            const int r = idx >> 4, ch = idx & 15;
            const uint32_t off = (uint32_t)(r * 256 + ((ch ^ (r & 7)) * 16));
            CP_ASYNC16(kbb + off, Kg + (tok0 + kb * 64 + r) * H_DIM + ch * 8);
            CP_ASYNC16(vbb + off, Vg + (tok0 + kb * 64 + r) * H_DIM + ch * 8);
        }
    };

    stage_kv(0); CP_COMMIT();

    float o[16][4];
#pragma unroll
    for (int jt = 0; jt < 16; jt++)
#pragma unroll
        for (int c = 0; c < 4; c++) o[jt][c] = 0.0f;
    float mA = -1e30f, mB = -1e30f, lA = 0.0f, lB = 0.0f;

    const int nb = 2 * qb + 2;
    const int rowA = qb * 128 + w * 16 + (l >> 2);
    const int wmax = qb * 128 + w * 16 + 15;

#pragma unroll 1
    for (int kb = 0; kb < nb; kb++) {
        if (kb + 1 < nb) { stage_kv(kb + 1); CP_COMMIT(); CP_WAIT(1); }
        else { CP_WAIT(0); }
        __syncthreads();

        if (kb * 64 <= wmax) {
            const uint32_t kbb = sb + 32768 + (kb & 1) * 32768;
            const uint32_t vbb = kbb + 16384;

            float s[8][4];
#pragma unroll
            for (int j = 0; j < 8; j++)
#pragma unroll
                for (int c = 0; c < 4; c++) s[j][c] = 0.0f;

#pragma unroll
            for (int ks = 0; ks < 8; ks++) {
                uint32_t a0, a1, a2, a3;
                {
                    const int row = w * 16 + (l & 15);
                    const int ch = ks * 2 + (l >> 4);
                    LDSM_X4(a0, a1, a2, a3, sb + row * 256 + ((ch ^ (row & 7)) * 16));
                }
                uint32_t bf[8][2];
#pragma unroll
                for (int jj = 0; jj < 4; jj++) {
                    const int nrow = jj * 16 + (l & 7) + ((l >> 4) & 1) * 8;
                    const int ch = ks * 2 + ((l >> 3) & 1);
                    LDSM_X4(bf[jj * 2][0], bf[jj * 2][1],
                            bf[jj * 2 + 1][0], bf[jj * 2 + 1][1],
                            kbb + nrow * 256 + ((ch ^ (nrow & 7)) * 16));
                }
#pragma unroll
                for (int j = 0; j < 8; j++)
                    MMA16816(s[j], a0, a1, a2, a3, bf[j][0], bf[j][1]);
            }

            if (kb >= 2 * qb) {
#pragma unroll
                for (int j = 0; j < 8; j++) {
                    const int col = kb * 64 + j * 8 + (l & 3) * 2;
                    if (col > rowA)     s[j][0] = -1e30f;
                    if (col + 1 > rowA) s[j][1] = -1e30f;
                    if (col > rowA + 8)     s[j][2] = -1e30f;
                    if (col + 1 > rowA + 8) s[j][3] = -1e30f;
                }
            }

            float mlA = -1e30f, mlB = -1e30f;
#pragma unroll
            for (int j = 0; j < 8; j++) {
                mlA = fmaxf(mlA, fmaxf(s[j][0], s[j][1]));
                mlB = fmaxf(mlB, fmaxf(s[j][2], s[j][3]));
            }
            mlA = fmaxf(mlA, __shfl_xor_sync(0xffffffffu, mlA, 1));
            mlA = fmaxf(mlA, __shfl_xor_sync(0xffffffffu, mlA, 2));
            mlB = fmaxf(mlB, __shfl_xor_sync(0xffffffffu, mlB, 1));
            mlB = fmaxf(mlB, __shfl_xor_sync(0xffffffffu, mlB, 2));

            const float mnA = fmaxf(mA, mlA), mnB = fmaxf(mB, mlB);
            const float aA = __expf((mA - mnA) * fscale);
            const float aB = __expf((mB - mnB) * fscale);
            mA = mnA; mB = mnB;

            uint32_t pA[8], pB[8];
            float sumA = 0.0f, sumB = 0.0f;
#pragma unroll
            for (int j = 0; j < 8; j++) {
                const float e0 = __expf((s[j][0] - mA) * fscale);
                const float e1 = __expf((s[j][1] - mA) * fscale);
                const float e2 = __expf((s[j][2] - mB) * fscale);
                const float e3 = __expf((s[j][3] - mB) * fscale);
                sumA += e0 + e1; sumB += e2 + e3;
                pA[j] = h2u(__floats2half2_rn(e0, e1));
                pB[j] = h2u(__floats2half2_rn(e2, e3));
            }
            sumA += __shfl_xor_sync(0xffffffffu, sumA, 1);
            sumA += __shfl_xor_sync(0xffffffffu, sumA, 2);
            sumB += __shfl_xor_sync(0xffffffffu, sumB, 1);
            sumB += __shfl_xor_sync(0xffffffffu, sumB, 2);
            lA = lA * aA + sumA;
            lB = lB * aB + sumB;

#pragma unroll
            for (int jt = 0; jt < 16; jt++) {
                o[jt][0] *= aA; o[jt][1] *= aA;
                o[jt][2] *= aB; o[jt][3] *= aB;
            }

#pragma unroll
            for (int ks2 = 0; ks2 < 4; ks2++) {
                const uint32_t pa0 = pA[2 * ks2],     pa1 = pB[2 * ks2];
                const uint32_t pa2 = pA[2 * ks2 + 1], pa3 = pB[2 * ks2 + 1];
                const int key = ks2 * 16 + (l & 7) + ((l >> 3) & 1) * 8;
#pragma unroll
                for (int u = 0; u < 8; u++) {
                    const int ch = 2 * u + (l >> 4);
                    uint32_t v0, v1, v2, v3;
                    LDSM_X4_T(v0, v1, v2, v3,
                              vbb + key * 256 + ((ch ^ (key & 7)) * 16));
                    MMA16816(o[2 * u],     pa0, pa1, pa2, pa3, v0, v1);
                    MMA16816(o[2 * u + 1], pa0, pa1, pa2, pa3, v2, v3);
                }
            }
        }
        __syncthreads();
    }

    const float invA = 1.0f / lA, invB = 1.0f / lB;
    const size_t rA = tok0 + qb * 128 + w * 16 + (l >> 2);
#pragma unroll
    for (int jt = 0; jt < 16; jt++) {
        const int col = h * H_DIM + jt * 8 + (l & 3) * 2;
        *reinterpret_cast<__half2*>(&Og[rA * D_MODEL + col]) =
            __floats2half2_rn(o[jt][0] * invA, o[jt][1] * invA);
        *reinterpret_cast<__half2*>(&Og[(rA + 8) * D_MODEL + col]) =
            __floats2half2_rn(o[jt][2] * invB, o[jt][3] * invB);
    }
}

// ---------------------------------------------------------------------------
extern "C" void kernel_launch(void* const* d_in, const int* in_sizes, int n_in,
                              void* d_out, int out_size)
{
    const float* x    = (const float*)d_in[0];
    const float* wq_w = (const float*)d_in[1];
    const float* wq_b = (const float*)d_in[2];
    const float* wk_w = (const float*)d_in[3];
    const float* wk_b = (const float*)d_in[4];
    const float* wv_w = (const float*)d_in[5];
    const float* wv_b = (const float*)d_in[6];
    const float* wo_w = (const float*)d_in[7];
    const float* wo_b = (const float*)d_in[8];
    float* out = (float*)d_out;

    __half *xh, *wqh, *wkh, *wvh, *woh, *qh, *kh, *vh, *ah;
    float* part;
    cudaGetSymbolAddress((void**)&xh,  g_xh);
    cudaGetSymbolAddress((void**)&wqh, g_wqh);
    cudaGetSymbolAddress((void**)&wkh, g_wkh);
    cudaGetSymbolAddress((void**)&wvh, g_wvh);
    cudaGetSymbolAddress((void**)&woh, g_woh);
    cudaGetSymbolAddress((void**)&qh,  g_qh);
    cudaGetSymbolAddress((void**)&kh,  g_kh);
    cudaGetSymbolAddress((void**)&vh,  g_vh);
    cudaGetSymbolAddress((void**)&ah,  g_ah);
    cudaGetSymbolAddress((void**)&part, g_kvpart);

    cudaFuncSetAttribute(qkv_kernel,
                         cudaFuncAttributeMaxDynamicSharedMemorySize, GEMM_SMEM);
    cudaFuncSetAttribute(oproj_kernel,
                         cudaFuncAttributeMaxDynamicSharedMemorySize, GEMM_SMEM);
    cudaFuncSetAttribute(attn_h_kernel,
                         cudaFuncAttributeMaxDynamicSharedMemorySize, ATTN_SMEM);

    // fp32 -> fp16 conversions (single merged launch)
    cvt_all_kernel<<<(int)(CVT_TOTAL / 1024), 256>>>(
        x, wq_w, wk_w, wv_w, wo_w, xh, wqh, wkh, wvh, woh);

    // Fused Q + split-K K/V projections
    qkv_kernel<<<1536, 128, GEMM_SMEM>>>(xh, wqh, wkh, wvh, wq_b, qh, part);
    kv_reduce_kernel<<<(2 * N_TOK * H_DIM) / 1024, 256>>>(part, wk_b, wv_b, kh, vh);

    // Causal flash attention (LPT order)
    attn_h_kernel<<<dim3(T_SEQ / 128, N_HEAD, 2), 256, ATTN_SMEM>>>(qh, kh, vh, ah);

    // Output projection (fp32 out)
    oproj_kernel<<<dim3(D_MODEL / 128, N_TOK / 128), 128, GEMM_SMEM>>>(
        ah, woh, wo_b, out);
}